// round 1
// baseline (speedup 1.0000x reference)
#include <cuda_runtime.h>
#include <cuda_bf16.h>
#include <cstdint>

#define NMAX 50000
#define DDIM 128

// Scratch (no cudaMalloc allowed): ~51.4 MB of static device globals.
__device__ float g_nbr[(size_t)NMAX * DDIM];   // scatter-sum accumulator
__device__ float g_deg[NMAX];                  // degree accumulator
__device__ float g_aggf[(size_t)NMAX * DDIM];  // agg_features after GEMM1

// ---------------------------------------------------------------------------
// Scatter: one warp per edge. 32 lanes x float4 = 128 floats.
// red.global.add.v4.f32 (sm_90+) quarters the red-op count vs scalar atomics.
// ---------------------------------------------------------------------------
__global__ __launch_bounds__(256) void scatter_kernel(
    const float* __restrict__ x,
    const int* __restrict__ erow,
    const int* __restrict__ ecol,
    int E)
{
    int gw = (blockIdx.x * blockDim.x + threadIdx.x) >> 5;
    int lane = threadIdx.x & 31;
    if (gw >= E) return;
    int r = erow[gw];
    int c = ecol[gw];
    float4 v = *reinterpret_cast<const float4*>(x + (size_t)r * DDIM + lane * 4);
    float* dst = g_nbr + (size_t)c * DDIM + lane * 4;
    asm volatile("red.global.add.v4.f32 [%0], {%1,%2,%3,%4};"
                 :: "l"(dst), "f"(v.x), "f"(v.y), "f"(v.z), "f"(v.w)
                 : "memory");
    if (lane == 0) atomicAdd(g_deg + c, 1.0f);
}

// ---------------------------------------------------------------------------
// GEMM1: aggf[M,128] = (nbr/deg) @ agg_W[128,128] + agg_b
// Tile: 64 rows x 128 cols, 256 threads, each thread 8x4 outputs.
// ---------------------------------------------------------------------------
__global__ __launch_bounds__(256) void gemm1_kernel(
    const float* __restrict__ aggW,
    const float* __restrict__ aggb,
    int M)
{
    __shared__ float As[64][20];    // [row][k] padded to 20 (16B-aligned)
    __shared__ float Bs[16][128];   // [k][col]

    const int tid  = threadIdx.x;
    const int tcol = tid & 31;      // 4-col group
    const int trow = tid >> 5;      // 8-row group
    const int base_row = blockIdx.x * 64;

    // A-load mapping: coalesced (4 lanes cover one row's 64B chunk)
    const int arow = tid >> 2;
    const int ak4  = (tid & 3) * 4;
    int ga_row = base_row + arow;
    if (ga_row >= M) ga_row = M - 1;
    const float rd = 1.0f / fmaxf(g_deg[ga_row], 1.0f);
    const float* a_src = g_nbr + (size_t)ga_row * DDIM;

    const int bk   = tid >> 5;
    const int bcol = (tid & 31) * 4;

    float acc[8][4];
    #pragma unroll
    for (int r = 0; r < 8; r++)
        #pragma unroll
        for (int c = 0; c < 4; c++) acc[r][c] = 0.f;

    for (int k0 = 0; k0 < DDIM; k0 += 16) {
        float4 a4 = *reinterpret_cast<const float4*>(a_src + k0 + ak4);
        a4.x *= rd; a4.y *= rd; a4.z *= rd; a4.w *= rd;
        *reinterpret_cast<float4*>(&As[arow][ak4]) = a4;
        #pragma unroll
        for (int i = 0; i < 2; i++) {
            int kb = bk + i * 8;
            *reinterpret_cast<float4*>(&Bs[kb][bcol]) =
                *reinterpret_cast<const float4*>(aggW + (size_t)(k0 + kb) * DDIM + bcol);
        }
        __syncthreads();
        #pragma unroll
        for (int kk = 0; kk < 16; kk++) {
            float4 b4 = *reinterpret_cast<const float4*>(&Bs[kk][tcol * 4]);
            float a[8];
            #pragma unroll
            for (int r = 0; r < 8; r++) a[r] = As[trow * 8 + r][kk];
            #pragma unroll
            for (int r = 0; r < 8; r++) {
                acc[r][0] = fmaf(a[r], b4.x, acc[r][0]);
                acc[r][1] = fmaf(a[r], b4.y, acc[r][1]);
                acc[r][2] = fmaf(a[r], b4.z, acc[r][2]);
                acc[r][3] = fmaf(a[r], b4.w, acc[r][3]);
            }
        }
        __syncthreads();
    }

    float4 bias = *reinterpret_cast<const float4*>(aggb + tcol * 4);
    #pragma unroll
    for (int r = 0; r < 8; r++) {
        int grow = base_row + trow * 8 + r;
        if (grow < M) {
            float4 o;
            o.x = acc[r][0] + bias.x;
            o.y = acc[r][1] + bias.y;
            o.z = acc[r][2] + bias.z;
            o.w = acc[r][3] + bias.w;
            *reinterpret_cast<float4*>(g_aggf + (size_t)grow * DDIM + tcol * 4) = o;
        }
    }
}

// ---------------------------------------------------------------------------
// GEMM2 + ReLU + LayerNorm:
//   out = LN(relu([x | aggf] @ W[256,128] + b)) * gamma + beta
// K=256 handled as 16 chunks of 16; chunks 0-7 read x, 8-15 read aggf.
// ---------------------------------------------------------------------------
__global__ __launch_bounds__(256) void gemm2_kernel(
    const float* __restrict__ x,
    const float* __restrict__ W,
    const float* __restrict__ b,
    const float* __restrict__ gamma,
    const float* __restrict__ beta,
    float* __restrict__ out,
    int M)
{
    __shared__ float As[64][20];
    __shared__ float Bs[16][128];
    __shared__ float Os[64][132];   // post-ReLU tile for LN

    const int tid  = threadIdx.x;
    const int tcol = tid & 31;
    const int trow = tid >> 5;
    const int base_row = blockIdx.x * 64;

    const int arow = tid >> 2;
    const int ak4  = (tid & 3) * 4;
    int ga_row = base_row + arow;
    if (ga_row >= M) ga_row = M - 1;
    const float* a_src_x = x + (size_t)ga_row * DDIM;
    const float* a_src_f = g_aggf + (size_t)ga_row * DDIM;

    const int bk   = tid >> 5;
    const int bcol = (tid & 31) * 4;

    float acc[8][4];
    #pragma unroll
    for (int r = 0; r < 8; r++)
        #pragma unroll
        for (int c = 0; c < 4; c++) acc[r][c] = 0.f;

    for (int k0 = 0; k0 < 2 * DDIM; k0 += 16) {
        const float* asrc = (k0 < DDIM) ? (a_src_x + k0) : (a_src_f + (k0 - DDIM));
        *reinterpret_cast<float4*>(&As[arow][ak4]) =
            *reinterpret_cast<const float4*>(asrc + ak4);
        #pragma unroll
        for (int i = 0; i < 2; i++) {
            int kb = bk + i * 8;
            *reinterpret_cast<float4*>(&Bs[kb][bcol]) =
                *reinterpret_cast<const float4*>(W + (size_t)(k0 + kb) * DDIM + bcol);
        }
        __syncthreads();
        #pragma unroll
        for (int kk = 0; kk < 16; kk++) {
            float4 b4 = *reinterpret_cast<const float4*>(&Bs[kk][tcol * 4]);
            float a[8];
            #pragma unroll
            for (int r = 0; r < 8; r++) a[r] = As[trow * 8 + r][kk];
            #pragma unroll
            for (int r = 0; r < 8; r++) {
                acc[r][0] = fmaf(a[r], b4.x, acc[r][0]);
                acc[r][1] = fmaf(a[r], b4.y, acc[r][1]);
                acc[r][2] = fmaf(a[r], b4.z, acc[r][2]);
                acc[r][3] = fmaf(a[r], b4.w, acc[r][3]);
            }
        }
        __syncthreads();
    }

    // epilogue: bias + ReLU into smem tile
    float4 bias = *reinterpret_cast<const float4*>(b + tcol * 4);
    #pragma unroll
    for (int r = 0; r < 8; r++) {
        float4 o;
        o.x = fmaxf(acc[r][0] + bias.x, 0.f);
        o.y = fmaxf(acc[r][1] + bias.y, 0.f);
        o.z = fmaxf(acc[r][2] + bias.z, 0.f);
        o.w = fmaxf(acc[r][3] + bias.w, 0.f);
        *reinterpret_cast<float4*>(&Os[trow * 8 + r][tcol * 4]) = o;
    }
    __syncthreads();

    // LayerNorm: warp w handles rows w*8 .. w*8+7, 4 floats per lane
    const int wid  = tid >> 5;
    const int lane = tid & 31;
    float4 g4 = *reinterpret_cast<const float4*>(gamma + lane * 4);
    float4 t4 = *reinterpret_cast<const float4*>(beta + lane * 4);
    #pragma unroll
    for (int i = 0; i < 8; i++) {
        int r = wid * 8 + i;
        float4 v = *reinterpret_cast<const float4*>(&Os[r][lane * 4]);
        float s  = v.x + v.y + v.z + v.w;
        float sq = v.x * v.x + v.y * v.y + v.z * v.z + v.w * v.w;
        #pragma unroll
        for (int o = 16; o > 0; o >>= 1) {
            s  += __shfl_xor_sync(0xFFFFFFFFu, s, o);
            sq += __shfl_xor_sync(0xFFFFFFFFu, sq, o);
        }
        float mean = s * (1.0f / DDIM);
        float var  = sq * (1.0f / DDIM) - mean * mean;
        float rstd = rsqrtf(var + 1e-5f);
        int grow = base_row + r;
        if (grow < M) {
            float4 o;
            o.x = (v.x - mean) * rstd * g4.x + t4.x;
            o.y = (v.y - mean) * rstd * g4.y + t4.y;
            o.z = (v.z - mean) * rstd * g4.z + t4.z;
            o.w = (v.w - mean) * rstd * g4.w + t4.w;
            *reinterpret_cast<float4*>(out + (size_t)grow * DDIM + lane * 4) = o;
        }
    }
}

// ---------------------------------------------------------------------------
// Launch: memset scratch -> scatter -> GEMM1 -> GEMM2(+LN). All graph-capturable.
// ---------------------------------------------------------------------------
extern "C" void kernel_launch(void* const* d_in, const int* in_sizes, int n_in,
                              void* d_out, int out_size)
{
    const float* x     = (const float*)d_in[0];
    const int*   ei    = (const int*)d_in[1];
    const float* aggW  = (const float*)d_in[2];
    const float* aggb  = (const float*)d_in[3];
    const float* W     = (const float*)d_in[4];
    const float* b     = (const float*)d_in[5];
    const float* gamma = (const float*)d_in[6];
    const float* beta  = (const float*)d_in[7];
    float* out = (float*)d_out;

    const int E = in_sizes[1] / 2;
    const int M = in_sizes[0] / DDIM;

    void *nbr_p = nullptr, *deg_p = nullptr;
    cudaGetSymbolAddress(&nbr_p, g_nbr);
    cudaGetSymbolAddress(&deg_p, g_deg);
    cudaMemsetAsync(nbr_p, 0, (size_t)M * DDIM * sizeof(float));
    cudaMemsetAsync(deg_p, 0, (size_t)M * sizeof(float));

    int sblocks = (E + 7) / 8;             // 8 warps (edges) per 256-thread block
    scatter_kernel<<<sblocks, 256>>>(x, ei, ei + E, E);

    int gblocks = (M + 63) / 64;
    gemm1_kernel<<<gblocks, 256>>>(aggW, aggb, M);
    gemm2_kernel<<<gblocks, 256>>>(x, W, b, gamma, beta, out, M);
}

// round 2
// speedup vs baseline: 1.5832x; 1.5832x over previous
#include <cuda_runtime.h>
#include <cuda_bf16.h>
#include <cstdint>

#define NMAX 50000
#define EMAX 800000
#define DDIM 128

// Static scratch (no cudaMalloc allowed)
__device__ float g_agg[(size_t)NMAX * DDIM];  // mean-aggregated features
__device__ float g_Wc[DDIM * DDIM];           // aggW @ W2   (fused weight)
__device__ float g_bc[DDIM];                  // b + aggb @ W2
__device__ int   g_degi[NMAX];                // degree histogram
__device__ int   g_off[NMAX];                 // CSR offsets (exclusive scan)
__device__ int   g_cur[NMAX];                 // running fill counters
__device__ int   g_bucket[EMAX];              // edge rows grouped by col

// ---------------------------------------------------------------------------
// 1) Degree histogram over destination nodes
// ---------------------------------------------------------------------------
__global__ __launch_bounds__(256) void hist_kernel(const int* __restrict__ ecol, int E)
{
    int e = blockIdx.x * blockDim.x + threadIdx.x;
    if (e < E) atomicAdd(g_degi + ecol[e], 1);
}

// ---------------------------------------------------------------------------
// 2) Exclusive scan of degrees (single block, Hillis-Steele per 1024 chunk)
// ---------------------------------------------------------------------------
__global__ __launch_bounds__(1024) void scan_kernel(int n)
{
    __shared__ int sdata[1024];
    __shared__ int carry;
    if (threadIdx.x == 0) carry = 0;
    __syncthreads();
    for (int base = 0; base < n; base += 1024) {
        int i = base + threadIdx.x;
        int v = (i < n) ? g_degi[i] : 0;
        sdata[threadIdx.x] = v;
        __syncthreads();
        #pragma unroll
        for (int o = 1; o < 1024; o <<= 1) {
            int t = (threadIdx.x >= o) ? sdata[threadIdx.x - o] : 0;
            __syncthreads();
            sdata[threadIdx.x] += t;
            __syncthreads();
        }
        if (i < n) g_off[i] = carry + sdata[threadIdx.x] - v;  // exclusive
        __syncthreads();
        if (threadIdx.x == 0) carry += sdata[1023];
        __syncthreads();
    }
}

// ---------------------------------------------------------------------------
// 3) Fill buckets: edge row-ids grouped by destination col
// ---------------------------------------------------------------------------
__global__ __launch_bounds__(256) void binfill_kernel(
    const int* __restrict__ erow, const int* __restrict__ ecol, int E)
{
    int e = blockIdx.x * blockDim.x + threadIdx.x;
    if (e >= E) return;
    int c = ecol[e];
    int p = atomicAdd(g_cur + c, 1);
    g_bucket[g_off[c] + p] = erow[e];
}

// ---------------------------------------------------------------------------
// 4) Gather-mean: one warp per node, register accumulation, no atomics.
// ---------------------------------------------------------------------------
__global__ __launch_bounds__(256) void gather_kernel(const float* __restrict__ x, int M)
{
    int w    = (blockIdx.x * blockDim.x + threadIdx.x) >> 5;
    int lane = threadIdx.x & 31;
    if (w >= M) return;
    int s = g_off[w];
    int d = g_degi[w];

    float4 acc = make_float4(0.f, 0.f, 0.f, 0.f);
    int j = 0;
    for (; j + 4 <= d; j += 4) {                 // 4-way MLP
        int r0 = g_bucket[s + j + 0];
        int r1 = g_bucket[s + j + 1];
        int r2 = g_bucket[s + j + 2];
        int r3 = g_bucket[s + j + 3];
        float4 v0 = *reinterpret_cast<const float4*>(x + (size_t)r0 * DDIM + lane * 4);
        float4 v1 = *reinterpret_cast<const float4*>(x + (size_t)r1 * DDIM + lane * 4);
        float4 v2 = *reinterpret_cast<const float4*>(x + (size_t)r2 * DDIM + lane * 4);
        float4 v3 = *reinterpret_cast<const float4*>(x + (size_t)r3 * DDIM + lane * 4);
        acc.x += v0.x + v1.x + v2.x + v3.x;
        acc.y += v0.y + v1.y + v2.y + v3.y;
        acc.z += v0.z + v1.z + v2.z + v3.z;
        acc.w += v0.w + v1.w + v2.w + v3.w;
    }
    for (; j < d; j++) {
        int r = g_bucket[s + j];
        float4 v = *reinterpret_cast<const float4*>(x + (size_t)r * DDIM + lane * 4);
        acc.x += v.x; acc.y += v.y; acc.z += v.z; acc.w += v.w;
    }
    float rd = 1.0f / fmaxf((float)d, 1.0f);
    float4 o = make_float4(acc.x * rd, acc.y * rd, acc.z * rd, acc.w * rd);
    *reinterpret_cast<float4*>(g_agg + (size_t)w * DDIM + lane * 4) = o;
}

// ---------------------------------------------------------------------------
// 5) Precompute fused weight Wc[k][n] = sum_j aggW[k][j] * W[128+j][n]
//    One block per k-row; thread n accumulates over j with coalesced W2 reads.
// ---------------------------------------------------------------------------
__global__ __launch_bounds__(128) void wc_kernel(
    const float* __restrict__ aggW, const float* __restrict__ W)
{
    int k = blockIdx.x;
    int n = threadIdx.x;
    float acc = 0.f;
    #pragma unroll 8
    for (int j = 0; j < DDIM; j++)
        acc = fmaf(aggW[k * DDIM + j], W[(size_t)(DDIM + j) * DDIM + n], acc);
    g_Wc[k * DDIM + n] = acc;
}

__global__ __launch_bounds__(128) void bc_kernel(
    const float* __restrict__ aggb, const float* __restrict__ W,
    const float* __restrict__ b)
{
    int n = threadIdx.x;
    float acc = b[n];
    #pragma unroll 8
    for (int j = 0; j < DDIM; j++)
        acc = fmaf(aggb[j], W[(size_t)(DDIM + j) * DDIM + n], acc);
    g_bc[n] = acc;
}

// ---------------------------------------------------------------------------
// 6) Fused GEMM + ReLU + LayerNorm:
//    out = LN(relu(x @ W1 + agg @ Wc + bc)) * gamma + beta
//    Tile 64x128, 256 threads, 8x4 per thread. K chunks 0-7: x/W1, 8-15: agg/Wc.
// ---------------------------------------------------------------------------
__global__ __launch_bounds__(256) void fused_gemm_kernel(
    const float* __restrict__ x,
    const float* __restrict__ W,
    const float* __restrict__ gamma,
    const float* __restrict__ beta,
    float* __restrict__ out,
    int M)
{
    __shared__ float As[64][20];
    __shared__ float Bs[16][128];
    __shared__ float Os[64][132];

    const int tid  = threadIdx.x;
    const int tcol = tid & 31;
    const int trow = tid >> 5;
    const int base_row = blockIdx.x * 64;

    const int arow = tid >> 2;
    const int ak4  = (tid & 3) * 4;
    int ga_row = base_row + arow;
    if (ga_row >= M) ga_row = M - 1;
    const float* a_src_x = x     + (size_t)ga_row * DDIM;
    const float* a_src_f = g_agg + (size_t)ga_row * DDIM;

    const int bk   = tid >> 5;
    const int bcol = (tid & 31) * 4;

    float acc[8][4];
    #pragma unroll
    for (int r = 0; r < 8; r++)
        #pragma unroll
        for (int c = 0; c < 4; c++) acc[r][c] = 0.f;

    for (int k0 = 0; k0 < 2 * DDIM; k0 += 16) {
        const bool first = (k0 < DDIM);
        const float* asrc = first ? (a_src_x + k0) : (a_src_f + (k0 - DDIM));
        const float* bmat = first ? (W + (size_t)k0 * DDIM)
                                  : (g_Wc + (size_t)(k0 - DDIM) * DDIM);
        *reinterpret_cast<float4*>(&As[arow][ak4]) =
            *reinterpret_cast<const float4*>(asrc + ak4);
        #pragma unroll
        for (int i = 0; i < 2; i++) {
            int kb = bk + i * 8;
            *reinterpret_cast<float4*>(&Bs[kb][bcol]) =
                *reinterpret_cast<const float4*>(bmat + (size_t)kb * DDIM + bcol);
        }
        __syncthreads();
        #pragma unroll
        for (int kk = 0; kk < 16; kk++) {
            float4 b4 = *reinterpret_cast<const float4*>(&Bs[kk][tcol * 4]);
            float a[8];
            #pragma unroll
            for (int r = 0; r < 8; r++) a[r] = As[trow * 8 + r][kk];
            #pragma unroll
            for (int r = 0; r < 8; r++) {
                acc[r][0] = fmaf(a[r], b4.x, acc[r][0]);
                acc[r][1] = fmaf(a[r], b4.y, acc[r][1]);
                acc[r][2] = fmaf(a[r], b4.z, acc[r][2]);
                acc[r][3] = fmaf(a[r], b4.w, acc[r][3]);
            }
        }
        __syncthreads();
    }

    // epilogue: fused bias + ReLU into smem tile
    float4 bias = *reinterpret_cast<const float4*>(g_bc + tcol * 4);
    #pragma unroll
    for (int r = 0; r < 8; r++) {
        float4 o;
        o.x = fmaxf(acc[r][0] + bias.x, 0.f);
        o.y = fmaxf(acc[r][1] + bias.y, 0.f);
        o.z = fmaxf(acc[r][2] + bias.z, 0.f);
        o.w = fmaxf(acc[r][3] + bias.w, 0.f);
        *reinterpret_cast<float4*>(&Os[trow * 8 + r][tcol * 4]) = o;
    }
    __syncthreads();

    // LayerNorm: warp w -> rows w*8..w*8+7, 4 floats/lane
    const int wid  = tid >> 5;
    const int lane = tid & 31;
    float4 g4 = *reinterpret_cast<const float4*>(gamma + lane * 4);
    float4 t4 = *reinterpret_cast<const float4*>(beta + lane * 4);
    #pragma unroll
    for (int i = 0; i < 8; i++) {
        int r = wid * 8 + i;
        float4 v = *reinterpret_cast<const float4*>(&Os[r][lane * 4]);
        float s  = v.x + v.y + v.z + v.w;
        float sq = v.x * v.x + v.y * v.y + v.z * v.z + v.w * v.w;
        #pragma unroll
        for (int o = 16; o > 0; o >>= 1) {
            s  += __shfl_xor_sync(0xFFFFFFFFu, s, o);
            sq += __shfl_xor_sync(0xFFFFFFFFu, sq, o);
        }
        float mean = s * (1.0f / DDIM);
        float var  = sq * (1.0f / DDIM) - mean * mean;
        float rstd = rsqrtf(var + 1e-5f);
        int grow = base_row + r;
        if (grow < M) {
            float4 o;
            o.x = (v.x - mean) * rstd * g4.x + t4.x;
            o.y = (v.y - mean) * rstd * g4.y + t4.y;
            o.z = (v.z - mean) * rstd * g4.z + t4.z;
            o.w = (v.w - mean) * rstd * g4.w + t4.w;
            *reinterpret_cast<float4*>(out + (size_t)grow * DDIM + lane * 4) = o;
        }
    }
}

// ---------------------------------------------------------------------------
extern "C" void kernel_launch(void* const* d_in, const int* in_sizes, int n_in,
                              void* d_out, int out_size)
{
    const float* x     = (const float*)d_in[0];
    const int*   ei    = (const int*)d_in[1];
    const float* aggW  = (const float*)d_in[2];
    const float* aggb  = (const float*)d_in[3];
    const float* W     = (const float*)d_in[4];
    const float* b     = (const float*)d_in[5];
    const float* gamma = (const float*)d_in[6];
    const float* beta  = (const float*)d_in[7];
    float* out = (float*)d_out;

    const int E = in_sizes[1] / 2;
    const int M = in_sizes[0] / DDIM;

    void *degi_p = nullptr, *cur_p = nullptr;
    cudaGetSymbolAddress(&degi_p, g_degi);
    cudaGetSymbolAddress(&cur_p,  g_cur);
    cudaMemsetAsync(degi_p, 0, (size_t)M * sizeof(int));
    cudaMemsetAsync(cur_p,  0, (size_t)M * sizeof(int));

    const int* erow = ei;
    const int* ecol = ei + E;

    int eb = (E + 255) / 256;
    hist_kernel<<<eb, 256>>>(ecol, E);
    scan_kernel<<<1, 1024>>>(M);
    binfill_kernel<<<eb, 256>>>(erow, ecol, E);

    int gb = (M * 32 + 255) / 256;   // one warp per node
    gather_kernel<<<gb, 256>>>(x, M);

    wc_kernel<<<DDIM, DDIM>>>(aggW, W);
    bc_kernel<<<1, DDIM>>>(aggb, W, b);

    int fb = (M + 63) / 64;
    fused_gemm_kernel<<<fb, 256>>>(x, W, gamma, beta, out, M);
}

// round 4
// speedup vs baseline: 1.9669x; 1.2423x over previous
#include <cuda_runtime.h>
#include <cuda_bf16.h>
#include <cstdint>

#define NMAX 50000
#define EMAX 800000
#define DDIM 128

// ---------------- static scratch (no allocation allowed) -------------------
__device__ float g_agg[(size_t)NMAX * DDIM];   // mean-aggregated features
__device__ float g_Wc[DDIM * DDIM];            // aggW @ W2 (fused weight)
__device__ float g_bc[DDIM];                   // b + aggb @ W2
__device__ int   g_degi[NMAX];
__device__ int   g_off[NMAX];
__device__ int   g_cur[NMAX];
__device__ int   g_bucket[EMAX];
// B = [W1 ; Wc]^T as bf16 hi/lo, layout [N=128][K=256] k-contiguous
__device__ __align__(16) __nv_bfloat16 g_Bh[128 * 256];
__device__ __align__(16) __nv_bfloat16 g_Bl[128 * 256];

// ---------------- 1) degree histogram --------------------------------------
__global__ __launch_bounds__(256) void hist_kernel(const int* __restrict__ ecol, int E)
{
    int e = blockIdx.x * blockDim.x + threadIdx.x;
    if (e < E) atomicAdd(g_degi + ecol[e], 1);
}

// ---------------- 2) exclusive scan (single block, serial chunks) ----------
__global__ __launch_bounds__(1024) void scan_kernel(int n)
{
    __shared__ int wsum[32];
    const int tid = threadIdx.x, lane = tid & 31, wid = tid >> 5;
    const int per = (n + 1023) / 1024;
    const int s0 = min(tid * per, n);
    const int s1 = min(s0 + per, n);
    int sum = 0;
    for (int i = s0; i < s1; i++) sum += g_degi[i];
    int v = sum;
    #pragma unroll
    for (int o = 1; o < 32; o <<= 1) {
        int t = __shfl_up_sync(0xFFFFFFFFu, v, o);
        if (lane >= o) v += t;
    }
    if (lane == 31) wsum[wid] = v;
    __syncthreads();
    if (wid == 0) {
        int w = wsum[lane];
        #pragma unroll
        for (int o = 1; o < 32; o <<= 1) {
            int t = __shfl_up_sync(0xFFFFFFFFu, w, o);
            if (lane >= o) w += t;
        }
        wsum[lane] = w;
    }
    __syncthreads();
    int run = v - sum + (wid ? wsum[wid - 1] : 0);
    for (int i = s0; i < s1; i++) {
        int d = g_degi[i];
        g_off[i] = run;
        g_cur[i] = run;      // binfill cursor seeded here (no memset needed)
        run += d;
    }
}

// ---------------- 3) bucket fill --------------------------------------------
__global__ __launch_bounds__(256) void binfill_kernel(
    const int* __restrict__ erow, const int* __restrict__ ecol, int E)
{
    int e = blockIdx.x * blockDim.x + threadIdx.x;
    if (e >= E) return;
    int p = atomicAdd(g_cur + ecol[e], 1);
    g_bucket[p] = erow[e];
}

// ---------------- 4) gather-mean (one warp per node) ------------------------
__global__ __launch_bounds__(256) void gather_kernel(const float* __restrict__ x, int M)
{
    int w    = (blockIdx.x * blockDim.x + threadIdx.x) >> 5;
    int lane = threadIdx.x & 31;
    if (w >= M) return;
    int s = g_off[w];
    int d = g_degi[w];
    float4 acc = make_float4(0.f, 0.f, 0.f, 0.f);
    int j = 0;
    for (; j + 4 <= d; j += 4) {
        int r0 = g_bucket[s + j + 0];
        int r1 = g_bucket[s + j + 1];
        int r2 = g_bucket[s + j + 2];
        int r3 = g_bucket[s + j + 3];
        float4 v0 = *reinterpret_cast<const float4*>(x + (size_t)r0 * DDIM + lane * 4);
        float4 v1 = *reinterpret_cast<const float4*>(x + (size_t)r1 * DDIM + lane * 4);
        float4 v2 = *reinterpret_cast<const float4*>(x + (size_t)r2 * DDIM + lane * 4);
        float4 v3 = *reinterpret_cast<const float4*>(x + (size_t)r3 * DDIM + lane * 4);
        acc.x += v0.x + v1.x + v2.x + v3.x;
        acc.y += v0.y + v1.y + v2.y + v3.y;
        acc.z += v0.z + v1.z + v2.z + v3.z;
        acc.w += v0.w + v1.w + v2.w + v3.w;
    }
    for (; j < d; j++) {
        int r = g_bucket[s + j];
        float4 v = *reinterpret_cast<const float4*>(x + (size_t)r * DDIM + lane * 4);
        acc.x += v.x; acc.y += v.y; acc.z += v.z; acc.w += v.w;
    }
    float rd = 1.0f / fmaxf((float)d, 1.0f);
    float4 o = make_float4(acc.x * rd, acc.y * rd, acc.z * rd, acc.w * rd);
    *reinterpret_cast<float4*>(g_agg + (size_t)w * DDIM + lane * 4) = o;
}

// ---------------- 5) fused-weight precompute --------------------------------
__global__ __launch_bounds__(128) void wc_kernel(
    const float* __restrict__ aggW, const float* __restrict__ W)
{
    int k = blockIdx.x, n = threadIdx.x;
    float acc = 0.f;
    #pragma unroll 8
    for (int j = 0; j < DDIM; j++)
        acc = fmaf(aggW[k * DDIM + j], W[(size_t)(DDIM + j) * DDIM + n], acc);
    g_Wc[k * DDIM + n] = acc;
}
__global__ __launch_bounds__(128) void bc_kernel(
    const float* __restrict__ aggb, const float* __restrict__ W,
    const float* __restrict__ b)
{
    int n = threadIdx.x;
    float acc = b[n];
    #pragma unroll 8
    for (int j = 0; j < DDIM; j++)
        acc = fmaf(aggb[j], W[(size_t)(DDIM + j) * DDIM + n], acc);
    g_bc[n] = acc;
}

// ---------------- 6) B transpose/split: [N=128][K=256] bf16 hi/lo ----------
__global__ __launch_bounds__(256) void prepB_kernel(const float* __restrict__ W)
{
    int idx = blockIdx.x * 256 + threadIdx.x;   // 0 .. 32767
    if (idx >= 128 * 256) return;
    int n = idx >> 8, k = idx & 255;
    float v = (k < DDIM) ? W[(size_t)k * DDIM + n]
                         : g_Wc[(size_t)(k - DDIM) * DDIM + n];
    __nv_bfloat16 h = __float2bfloat16(v);
    __nv_bfloat16 l = __float2bfloat16(v - __bfloat162float(h));
    g_Bh[idx] = h;
    g_Bl[idx] = l;
}

// ---------------- 7) mma.sync GEMM + ReLU + LayerNorm -----------------------
// out = LN(relu(x @ W1 + agg @ Wc + bc)) * gamma + beta
// 3-pass bf16 split (Ah*Bh + Ah*Bl + Al*Bh), fp32 accum, m16n8k16 HMMA.
// CTA tile 128x128, 8 warps as 4(m) x 2(n); warp tile 32x64.
#define A_STRIDE_B 272          // 128 bf16 (256B) + 16B pad  -> conflict-free ldmatrix
#define B_STRIDE_B 528          // 256 bf16 (512B) + 16B pad
#define SM_BIAS   0
#define SM_GAMMA  512
#define SM_BETA   1024
#define SM_AH     1536
#define SM_AL     (SM_AH + 128 * A_STRIDE_B)        // +34816
#define SM_BH     (SM_AL + 128 * A_STRIDE_B)
#define SM_BL     (SM_BH + 128 * B_STRIDE_B)        // +67584
#define SM_TOTAL  (SM_BL + 128 * B_STRIDE_B)        // 206336 bytes
#define SM_STAGE  SM_AH                              // 128*132*4 = 67584 B (fits AH+AL)

__device__ __forceinline__ uint32_t smem_u32(const void* p) {
    uint32_t a;
    asm("{ .reg .u64 t; cvta.to.shared.u64 t, %1; cvt.u32.u64 %0, t; }"
        : "=r"(a) : "l"(p));
    return a;
}
__device__ __forceinline__ void ldmx4(uint32_t* r, uint32_t addr) {
    asm volatile("ldmatrix.sync.aligned.m8n8.x4.shared.b16 {%0,%1,%2,%3}, [%4];"
                 : "=r"(r[0]), "=r"(r[1]), "=r"(r[2]), "=r"(r[3]) : "r"(addr));
}
__device__ __forceinline__ void mma_bf16(float* c, const uint32_t* a, uint32_t b0, uint32_t b1) {
    asm volatile(
        "mma.sync.aligned.m16n8k16.row.col.f32.bf16.bf16.f32 "
        "{%0,%1,%2,%3}, {%4,%5,%6,%7}, {%8,%9}, {%0,%1,%2,%3};"
        : "+f"(c[0]), "+f"(c[1]), "+f"(c[2]), "+f"(c[3])
        : "r"(a[0]), "r"(a[1]), "r"(a[2]), "r"(a[3]), "r"(b0), "r"(b1));
}

__global__ __launch_bounds__(256, 1) void mma_gemm_kernel(
    const float* __restrict__ x,
    const float* __restrict__ gamma,
    const float* __restrict__ beta,
    float* __restrict__ out,
    int M)
{
    extern __shared__ char smem[];
    const uint32_t sb = smem_u32(smem);
    const int tid  = threadIdx.x;
    const int wid  = tid >> 5;
    const int lane = tid & 31;
    const int base_row = blockIdx.x * 128;
    const int warp_m = wid & 3;      // 32-row group
    const int warp_n = wid >> 2;     // 64-col group

    // bias/gamma/beta -> smem
    if (tid < 32) {
        reinterpret_cast<float4*>(smem + SM_BIAS)[tid]  =
            reinterpret_cast<const float4*>(g_bc)[tid];
        reinterpret_cast<float4*>(smem + SM_GAMMA)[tid] =
            reinterpret_cast<const float4*>(gamma)[tid];
        reinterpret_cast<float4*>(smem + SM_BETA)[tid]  =
            reinterpret_cast<const float4*>(beta)[tid];
    }
    // B hi/lo -> smem (row n: 512B data + pad)
    {
        const uint4* bh = reinterpret_cast<const uint4*>(g_Bh);
        const uint4* bl = reinterpret_cast<const uint4*>(g_Bl);
        #pragma unroll
        for (int i = 0; i < 16; i++) {
            int idx = tid + i * 256;            // 0..4095 uint4
            int n = idx >> 5, q = idx & 31;
            *reinterpret_cast<uint4*>(smem + SM_BH + n * B_STRIDE_B + q * 16) = bh[idx];
            *reinterpret_cast<uint4*>(smem + SM_BL + n * B_STRIDE_B + q * 16) = bl[idx];
        }
    }

    // A-half fill: 128 rows x 128 k fp32 -> bf16 hi/lo
    auto fill_half = [&](const float* __restrict__ src) {
        #pragma unroll
        for (int i = 0; i < 16; i++) {
            int idx = tid + i * 256;            // 0..4095 float4 slots
            int row = idx >> 5;
            int kq  = (idx & 31) * 4;
            int grow = base_row + row;
            if (grow >= M) grow = M - 1;
            float4 v = *reinterpret_cast<const float4*>(src + (size_t)grow * DDIM + kq);
            __nv_bfloat16 h0 = __float2bfloat16(v.x);
            __nv_bfloat16 h1 = __float2bfloat16(v.y);
            __nv_bfloat16 h2 = __float2bfloat16(v.z);
            __nv_bfloat16 h3 = __float2bfloat16(v.w);
            __nv_bfloat16 l0 = __float2bfloat16(v.x - __bfloat162float(h0));
            __nv_bfloat16 l1 = __float2bfloat16(v.y - __bfloat162float(h1));
            __nv_bfloat16 l2 = __float2bfloat16(v.z - __bfloat162float(h2));
            __nv_bfloat16 l3 = __float2bfloat16(v.w - __bfloat162float(h3));
            uint2 hw, lw;
            hw.x = ((uint32_t)__bfloat16_as_ushort(h1) << 16) | __bfloat16_as_ushort(h0);
            hw.y = ((uint32_t)__bfloat16_as_ushort(h3) << 16) | __bfloat16_as_ushort(h2);
            lw.x = ((uint32_t)__bfloat16_as_ushort(l1) << 16) | __bfloat16_as_ushort(l0);
            lw.y = ((uint32_t)__bfloat16_as_ushort(l3) << 16) | __bfloat16_as_ushort(l2);
            uint32_t off = (uint32_t)row * A_STRIDE_B + (uint32_t)kq * 2;
            *reinterpret_cast<uint2*>(smem + SM_AH + off) = hw;
            *reinterpret_cast<uint2*>(smem + SM_AL + off) = lw;
        }
    };

    float acc[2][8][4];
    #pragma unroll
    for (int i = 0; i < 2; i++)
        #pragma unroll
        for (int j = 0; j < 8; j++)
            #pragma unroll
            for (int c = 0; c < 4; c++) acc[i][j][c] = 0.f;

    // ldmatrix lane address components
    const int a_row_lo = (lane & 7) + ((lane >> 3) & 1) * 8;   // 0..15 within 16-row frag
    const int a_koff   = ((lane >> 4) & 1) * 8;                 // 0 or 8
    const int b_nrow   = warp_n * 64 + (lane & 7) + ((lane >> 4) & 1) * 8; // within pair base
    const int b_koff   = ((lane >> 3) & 1) * 8;

    // per-half compute: 8 k-chunks of 16 over A smem; B k index = h*128 + ...
    auto compute_half = [&](int h) {
        #pragma unroll
        for (int kc = 0; kc < 8; kc++) {
            const int kA = kc * 16 + a_koff;
            const int kB = h * 128 + kc * 16 + b_koff;
            uint32_t ah[2][4], al[2][4];
            #pragma unroll
            for (int i = 0; i < 2; i++) {
                int row = warp_m * 32 + i * 16 + a_row_lo;
                uint32_t off = (uint32_t)row * A_STRIDE_B + (uint32_t)kA * 2;
                ldmx4(ah[i], sb + SM_AH + off);
                ldmx4(al[i], sb + SM_AL + off);
            }
            uint32_t bh[4][4], bl[4][4];
            #pragma unroll
            for (int p = 0; p < 4; p++) {
                uint32_t off = (uint32_t)(b_nrow + p * 16) * B_STRIDE_B + (uint32_t)kB * 2;
                ldmx4(bh[p], sb + SM_BH + off);
                ldmx4(bl[p], sb + SM_BL + off);
            }
            #pragma unroll
            for (int i = 0; i < 2; i++)
                #pragma unroll
                for (int p = 0; p < 4; p++) {
                    mma_bf16(acc[i][2 * p],     ah[i], bh[p][0], bh[p][1]);
                    mma_bf16(acc[i][2 * p + 1], ah[i], bh[p][2], bh[p][3]);
                    mma_bf16(acc[i][2 * p],     ah[i], bl[p][0], bl[p][1]);
                    mma_bf16(acc[i][2 * p + 1], ah[i], bl[p][2], bl[p][3]);
                    mma_bf16(acc[i][2 * p],     al[i], bh[p][0], bh[p][1]);
                    mma_bf16(acc[i][2 * p + 1], al[i], bh[p][2], bh[p][3]);
                }
        }
    };

    fill_half(x);
    __syncthreads();
    compute_half(0);
    __syncthreads();
    fill_half(g_agg);
    __syncthreads();
    compute_half(1);
    __syncthreads();               // all warps done reading A region

    // stage raw accumulators into smem tile [128][132] (reuses A region)
    float* stg = reinterpret_cast<float*>(smem + SM_STAGE);
    #pragma unroll
    for (int i = 0; i < 2; i++) {
        int row0 = warp_m * 32 + i * 16 + (lane >> 2);
        #pragma unroll
        for (int j = 0; j < 8; j++) {
            int col = warp_n * 64 + j * 8 + (lane & 3) * 2;
            *reinterpret_cast<float2*>(stg + row0 * 132 + col) =
                make_float2(acc[i][j][0], acc[i][j][1]);
            *reinterpret_cast<float2*>(stg + (row0 + 8) * 132 + col) =
                make_float2(acc[i][j][2], acc[i][j][3]);
        }
    }
    __syncthreads();

    // LN: warp wid handles rows wid*16 .. +15; lane owns 4 cols
    float4 b4 = *reinterpret_cast<const float4*>(smem + SM_BIAS  + lane * 16);
    float4 g4 = *reinterpret_cast<const float4*>(smem + SM_GAMMA + lane * 16);
    float4 t4 = *reinterpret_cast<const float4*>(smem + SM_BETA  + lane * 16);
    #pragma unroll
    for (int ii = 0; ii < 16; ii++) {
        int r = wid * 16 + ii;
        float4 v = *reinterpret_cast<const float4*>(stg + r * 132 + lane * 4);
        v.x = fmaxf(v.x + b4.x, 0.f);
        v.y = fmaxf(v.y + b4.y, 0.f);
        v.z = fmaxf(v.z + b4.z, 0.f);
        v.w = fmaxf(v.w + b4.w, 0.f);
        float s  = v.x + v.y + v.z + v.w;
        float sq = v.x * v.x + v.y * v.y + v.z * v.z + v.w * v.w;
        #pragma unroll
        for (int o = 16; o > 0; o >>= 1) {
            s  += __shfl_xor_sync(0xFFFFFFFFu, s, o);
            sq += __shfl_xor_sync(0xFFFFFFFFu, sq, o);
        }
        float mean = s * (1.0f / DDIM);
        float var  = sq * (1.0f / DDIM) - mean * mean;
        float rstd = rsqrtf(var + 1e-5f);
        int grow = base_row + r;
        if (grow < M) {
            float4 o;
            o.x = (v.x - mean) * rstd * g4.x + t4.x;
            o.y = (v.y - mean) * rstd * g4.y + t4.y;
            o.z = (v.z - mean) * rstd * g4.z + t4.z;
            o.w = (v.w - mean) * rstd * g4.w + t4.w;
            *reinterpret_cast<float4*>(out + (size_t)grow * DDIM + lane * 4) = o;
        }
    }
}

// ---------------------------------------------------------------------------
extern "C" void kernel_launch(void* const* d_in, const int* in_sizes, int n_in,
                              void* d_out, int out_size)
{
    const float* x     = (const float*)d_in[0];
    const int*   ei    = (const int*)d_in[1];
    const float* aggW  = (const float*)d_in[2];
    const float* aggb  = (const float*)d_in[3];
    const float* W     = (const float*)d_in[4];
    const float* b     = (const float*)d_in[5];
    const float* gamma = (const float*)d_in[6];
    const float* beta  = (const float*)d_in[7];
    float* out = (float*)d_out;

    const int E = in_sizes[1] / 2;
    const int M = in_sizes[0] / DDIM;

    cudaFuncSetAttribute(mma_gemm_kernel,
                         cudaFuncAttributeMaxDynamicSharedMemorySize, SM_TOTAL);

    void* degi_p = nullptr;
    cudaGetSymbolAddress(&degi_p, g_degi);
    cudaMemsetAsync(degi_p, 0, (size_t)M * sizeof(int));

    const int* erow = ei;
    const int* ecol = ei + E;
    int eb = (E + 255) / 256;

    hist_kernel<<<eb, 256>>>(ecol, E);
    scan_kernel<<<1, 1024>>>(M);
    binfill_kernel<<<eb, 256>>>(erow, ecol, E);
    gather_kernel<<<(M * 32 + 255) / 256, 256>>>(x, M);

    wc_kernel<<<DDIM, DDIM>>>(aggW, W);
    bc_kernel<<<1, DDIM>>>(aggb, W, b);
    prepB_kernel<<<128, 256>>>(W);

    mma_gemm_kernel<<<(M + 127) / 128, 256, SM_TOTAL>>>(x, gamma, beta, out, M);
}

// round 6
// speedup vs baseline: 2.0068x; 1.0203x over previous
#include <cuda_runtime.h>
#include <cuda_bf16.h>
#include <cstdint>

#define NMAX 50000
#define EMAX 800000
#define DDIM 128

// ---------------- static scratch (no allocation allowed) -------------------
__device__ float g_agg[(size_t)NMAX * DDIM];
__device__ float g_Wc[DDIM * DDIM];
__device__ float g_bc[DDIM];
__device__ int   g_degi[NMAX];
__device__ int   g_off[NMAX];
__device__ int   g_cur[NMAX];
__device__ int   g_bucket[EMAX];
// B = [W1 ; Wc]^T as bf16 hi/lo, layout [N=128][K=256] k-contiguous
__device__ __align__(16) __nv_bfloat16 g_Bh[128 * 256];
__device__ __align__(16) __nv_bfloat16 g_Bl[128 * 256];

// ---------------- 1) degree histogram --------------------------------------
__global__ __launch_bounds__(256) void hist_kernel(const int* __restrict__ ecol, int E)
{
    int e = blockIdx.x * blockDim.x + threadIdx.x;
    if (e < E) atomicAdd(g_degi + ecol[e], 1);
}

// ---------------- 2) exclusive scan (single block, serial chunks) ----------
__global__ __launch_bounds__(1024) void scan_kernel(int n)
{
    __shared__ int wsum[32];
    const int tid = threadIdx.x, lane = tid & 31, wid = tid >> 5;
    const int per = (n + 1023) / 1024;
    const int s0 = min(tid * per, n);
    const int s1 = min(s0 + per, n);
    int sum = 0;
    for (int i = s0; i < s1; i++) sum += g_degi[i];
    int v = sum;
    #pragma unroll
    for (int o = 1; o < 32; o <<= 1) {
        int t = __shfl_up_sync(0xFFFFFFFFu, v, o);
        if (lane >= o) v += t;
    }
    if (lane == 31) wsum[wid] = v;
    __syncthreads();
    if (wid == 0) {
        int w = wsum[lane];
        #pragma unroll
        for (int o = 1; o < 32; o <<= 1) {
            int t = __shfl_up_sync(0xFFFFFFFFu, w, o);
            if (lane >= o) w += t;
        }
        wsum[lane] = w;
    }
    __syncthreads();
    int run = v - sum + (wid ? wsum[wid - 1] : 0);
    for (int i = s0; i < s1; i++) {
        int d = g_degi[i];
        g_off[i] = run;
        g_cur[i] = run;
        run += d;
    }
}

// ---------------- 3) bucket fill --------------------------------------------
__global__ __launch_bounds__(256) void binfill_kernel(
    const int* __restrict__ erow, const int* __restrict__ ecol, int E)
{
    int e = blockIdx.x * blockDim.x + threadIdx.x;
    if (e >= E) return;
    int p = atomicAdd(g_cur + ecol[e], 1);
    g_bucket[p] = erow[e];
}

// ---------------- 4) gather-mean (one warp per node) ------------------------
__global__ __launch_bounds__(256) void gather_kernel(const float* __restrict__ x, int M)
{
    int w    = (blockIdx.x * blockDim.x + threadIdx.x) >> 5;
    int lane = threadIdx.x & 31;
    if (w >= M) return;
    int s = g_off[w];
    int d = g_degi[w];
    float4 acc = make_float4(0.f, 0.f, 0.f, 0.f);
    int j = 0;
    for (; j + 4 <= d; j += 4) {
        int r0 = g_bucket[s + j + 0];
        int r1 = g_bucket[s + j + 1];
        int r2 = g_bucket[s + j + 2];
        int r3 = g_bucket[s + j + 3];
        float4 v0 = *reinterpret_cast<const float4*>(x + (size_t)r0 * DDIM + lane * 4);
        float4 v1 = *reinterpret_cast<const float4*>(x + (size_t)r1 * DDIM + lane * 4);
        float4 v2 = *reinterpret_cast<const float4*>(x + (size_t)r2 * DDIM + lane * 4);
        float4 v3 = *reinterpret_cast<const float4*>(x + (size_t)r3 * DDIM + lane * 4);
        acc.x += v0.x + v1.x + v2.x + v3.x;
        acc.y += v0.y + v1.y + v2.y + v3.y;
        acc.z += v0.z + v1.z + v2.z + v3.z;
        acc.w += v0.w + v1.w + v2.w + v3.w;
    }
    for (; j < d; j++) {
        int r = g_bucket[s + j];
        float4 v = *reinterpret_cast<const float4*>(x + (size_t)r * DDIM + lane * 4);
        acc.x += v.x; acc.y += v.y; acc.z += v.z; acc.w += v.w;
    }
    float rd = 1.0f / fmaxf((float)d, 1.0f);
    float4 o = make_float4(acc.x * rd, acc.y * rd, acc.z * rd, acc.w * rd);
    *reinterpret_cast<float4*>(g_agg + (size_t)w * DDIM + lane * 4) = o;
}

// ---------------- 5) fused-weight precompute (wc + bc merged) ---------------
__global__ __launch_bounds__(128) void wcbc_kernel(
    const float* __restrict__ aggW, const float* __restrict__ aggb,
    const float* __restrict__ W,    const float* __restrict__ b)
{
    int k = blockIdx.x, n = threadIdx.x;
    float acc = 0.f;
    #pragma unroll 8
    for (int j = 0; j < DDIM; j++)
        acc = fmaf(aggW[k * DDIM + j], W[(size_t)(DDIM + j) * DDIM + n], acc);
    g_Wc[k * DDIM + n] = acc;
    if (blockIdx.x == 0) {
        float bcv = b[n];
        #pragma unroll 8
        for (int j = 0; j < DDIM; j++)
            bcv = fmaf(aggb[j], W[(size_t)(DDIM + j) * DDIM + n], bcv);
        g_bc[n] = bcv;
    }
}

// ---------------- 6) B transpose/split: [N=128][K=256] bf16 hi/lo ----------
__global__ __launch_bounds__(256) void prepB_kernel(const float* __restrict__ W)
{
    int idx = blockIdx.x * 256 + threadIdx.x;
    if (idx >= 128 * 256) return;
    int n = idx >> 8, k = idx & 255;
    float v = (k < DDIM) ? W[(size_t)k * DDIM + n]
                         : g_Wc[(size_t)(k - DDIM) * DDIM + n];
    __nv_bfloat16 h = __float2bfloat16(v);
    __nv_bfloat16 l = __float2bfloat16(v - __bfloat162float(h));
    g_Bh[idx] = h;
    g_Bl[idx] = l;
}

// ---------------- 7) fused GEMM + ReLU + LayerNorm (512 threads) ------------
// out = LN(relu(x @ W1 + agg @ Wc + bc)) * gamma + beta
// 3-pass bf16 split (Ah*Bh + Ah*Bl + Al*Bh), fp32 accum, m16n8k16.
// CTA tile 128x128; 16 warps as 4(m) x 4(n); warp tile 32x32.
// B [N=128][K=256] resident in smem; A refilled per K-half.
#define A_STRIDE_B 272          // 128 bf16 + 16B pad
#define B_STRIDE_B 528          // 256 bf16 + 16B pad
#define SM_BIAS   0
#define SM_GAMMA  512
#define SM_BETA   1024
#define SM_AH     1536
#define SM_AL     (SM_AH + 128 * A_STRIDE_B)        // +34816
#define SM_BH     (SM_AL + 128 * A_STRIDE_B)
#define SM_BL     (SM_BH + 128 * B_STRIDE_B)        // +67584
#define SM_TOTAL  (SM_BL + 128 * B_STRIDE_B)        // 206336 B
#define SM_STAGE  SM_AH                              // 128*132*4 = 67584 B

__device__ __forceinline__ uint32_t smem_u32(const void* p) {
    uint32_t a;
    asm("{ .reg .u64 t; cvta.to.shared.u64 t, %1; cvt.u32.u64 %0, t; }"
        : "=r"(a) : "l"(p));
    return a;
}
__device__ __forceinline__ void ldmx4(uint32_t* r, uint32_t addr) {
    asm volatile("ldmatrix.sync.aligned.m8n8.x4.shared.b16 {%0,%1,%2,%3}, [%4];"
                 : "=r"(r[0]), "=r"(r[1]), "=r"(r[2]), "=r"(r[3]) : "r"(addr));
}
__device__ __forceinline__ void mma_bf16(float* c, const uint32_t* a, uint32_t b0, uint32_t b1) {
    asm volatile(
        "mma.sync.aligned.m16n8k16.row.col.f32.bf16.bf16.f32 "
        "{%0,%1,%2,%3}, {%4,%5,%6,%7}, {%8,%9}, {%0,%1,%2,%3};"
        : "+f"(c[0]), "+f"(c[1]), "+f"(c[2]), "+f"(c[3])
        : "r"(a[0]), "r"(a[1]), "r"(a[2]), "r"(a[3]), "r"(b0), "r"(b1));
}

__global__ __launch_bounds__(512, 1) void mma_gemm_kernel(
    const float* __restrict__ x,
    const float* __restrict__ gamma,
    const float* __restrict__ beta,
    float* __restrict__ out,
    int M)
{
    extern __shared__ char smem[];
    const uint32_t sb = smem_u32(smem);
    const int tid  = threadIdx.x;
    const int wid  = tid >> 5;
    const int lane = tid & 31;
    const int base_row = blockIdx.x * 128;
    const int warp_m = wid & 3;      // 32-row group
    const int warp_n = wid >> 2;     // 32-col group

    if (tid < 32) {
        reinterpret_cast<float4*>(smem + SM_BIAS)[tid]  =
            reinterpret_cast<const float4*>(g_bc)[tid];
        reinterpret_cast<float4*>(smem + SM_GAMMA)[tid] =
            reinterpret_cast<const float4*>(gamma)[tid];
        reinterpret_cast<float4*>(smem + SM_BETA)[tid]  =
            reinterpret_cast<const float4*>(beta)[tid];
    }
    // B hi/lo -> smem: 128 rows x 512B (full K)
    #pragma unroll
    for (int i = 0; i < 8; i++) {
        int idx = tid + i * 512;            // 0..4095 uint4
        int n = idx >> 5, q = idx & 31;
        *reinterpret_cast<uint4*>(smem + SM_BH + n * B_STRIDE_B + q * 16) =
            *reinterpret_cast<const uint4*>(g_Bh + n * 256 + q * 8);
        *reinterpret_cast<uint4*>(smem + SM_BL + n * B_STRIDE_B + q * 16) =
            *reinterpret_cast<const uint4*>(g_Bl + n * 256 + q * 8);
    }

    // A-half fill: 128 rows x 128 k fp32 -> bf16 hi/lo
    auto fill_half = [&](const float* __restrict__ src) {
        #pragma unroll
        for (int i = 0; i < 8; i++) {
            int idx = tid + i * 512;        // 0..4095 float4 slots
            int row = idx >> 5;
            int kq  = (idx & 31) * 4;
            int grow = base_row + row;
            if (grow >= M) grow = M - 1;
            float4 v = *reinterpret_cast<const float4*>(src + (size_t)grow * DDIM + kq);
            __nv_bfloat16 h0 = __float2bfloat16(v.x);
            __nv_bfloat16 h1 = __float2bfloat16(v.y);
            __nv_bfloat16 h2 = __float2bfloat16(v.z);
            __nv_bfloat16 h3 = __float2bfloat16(v.w);
            __nv_bfloat16 l0 = __float2bfloat16(v.x - __bfloat162float(h0));
            __nv_bfloat16 l1 = __float2bfloat16(v.y - __bfloat162float(h1));
            __nv_bfloat16 l2 = __float2bfloat16(v.z - __bfloat162float(h2));
            __nv_bfloat16 l3 = __float2bfloat16(v.w - __bfloat162float(h3));
            uint2 hw, lw;
            hw.x = ((uint32_t)__bfloat16_as_ushort(h1) << 16) | __bfloat16_as_ushort(h0);
            hw.y = ((uint32_t)__bfloat16_as_ushort(h3) << 16) | __bfloat16_as_ushort(h2);
            lw.x = ((uint32_t)__bfloat16_as_ushort(l1) << 16) | __bfloat16_as_ushort(l0);
            lw.y = ((uint32_t)__bfloat16_as_ushort(l3) << 16) | __bfloat16_as_ushort(l2);
            uint32_t off = (uint32_t)row * A_STRIDE_B + (uint32_t)kq * 2;
            *reinterpret_cast<uint2*>(smem + SM_AH + off) = hw;
            *reinterpret_cast<uint2*>(smem + SM_AL + off) = lw;
        }
    };

    float acc[2][4][4];
    #pragma unroll
    for (int i = 0; i < 2; i++)
        #pragma unroll
        for (int j = 0; j < 4; j++)
            #pragma unroll
            for (int c = 0; c < 4; c++) acc[i][j][c] = 0.f;

    const int a_row_lo = (lane & 7) + ((lane >> 3) & 1) * 8;
    const int a_koff   = ((lane >> 4) & 1) * 8;
    const int b_nrow   = warp_n * 32 + (lane & 7) + ((lane >> 4) & 1) * 8;
    const int b_koff   = ((lane >> 3) & 1) * 8;

    auto compute_half = [&](int h) {
        #pragma unroll
        for (int kc = 0; kc < 8; kc++) {
            const int kA = kc * 16 + a_koff;
            const int kB = h * 128 + kc * 16 + b_koff;
            uint32_t ah[2][4], al[2][4];
            #pragma unroll
            for (int i = 0; i < 2; i++) {
                int row = warp_m * 32 + i * 16 + a_row_lo;
                uint32_t off = (uint32_t)row * A_STRIDE_B + (uint32_t)kA * 2;
                ldmx4(ah[i], sb + SM_AH + off);
                ldmx4(al[i], sb + SM_AL + off);
            }
            uint32_t bh[2][4], bl[2][4];
            #pragma unroll
            for (int p = 0; p < 2; p++) {
                uint32_t off = (uint32_t)(b_nrow + p * 16) * B_STRIDE_B + (uint32_t)kB * 2;
                ldmx4(bh[p], sb + SM_BH + off);
                ldmx4(bl[p], sb + SM_BL + off);
            }
            #pragma unroll
            for (int i = 0; i < 2; i++)
                #pragma unroll
                for (int p = 0; p < 2; p++) {
                    mma_bf16(acc[i][2 * p],     ah[i], bh[p][0], bh[p][1]);
                    mma_bf16(acc[i][2 * p + 1], ah[i], bh[p][2], bh[p][3]);
                    mma_bf16(acc[i][2 * p],     ah[i], bl[p][0], bl[p][1]);
                    mma_bf16(acc[i][2 * p + 1], ah[i], bl[p][2], bl[p][3]);
                    mma_bf16(acc[i][2 * p],     al[i], bh[p][0], bh[p][1]);
                    mma_bf16(acc[i][2 * p + 1], al[i], bh[p][2], bh[p][3]);
                }
        }
    };

    fill_half(x);
    __syncthreads();
    compute_half(0);
    __syncthreads();
    fill_half(g_agg);
    __syncthreads();
    compute_half(1);
    __syncthreads();              // done reading A region

    // stage accumulators [128][132] (reuses A region)
    float* stg = reinterpret_cast<float*>(smem + SM_STAGE);
    #pragma unroll
    for (int i = 0; i < 2; i++) {
        int row0 = warp_m * 32 + i * 16 + (lane >> 2);
        #pragma unroll
        for (int j = 0; j < 4; j++) {
            int col = warp_n * 32 + j * 8 + (lane & 3) * 2;
            *reinterpret_cast<float2*>(stg + row0 * 132 + col) =
                make_float2(acc[i][j][0], acc[i][j][1]);
            *reinterpret_cast<float2*>(stg + (row0 + 8) * 132 + col) =
                make_float2(acc[i][j][2], acc[i][j][3]);
        }
    }
    __syncthreads();

    // bias + ReLU + LN; warp wid -> rows wid*8..+7, lane owns 4 cols
    float4 b4 = *reinterpret_cast<const float4*>(smem + SM_BIAS  + lane * 16);
    float4 g4 = *reinterpret_cast<const float4*>(smem + SM_GAMMA + lane * 16);
    float4 t4 = *reinterpret_cast<const float4*>(smem + SM_BETA  + lane * 16);
    #pragma unroll
    for (int ii = 0; ii < 8; ii++) {
        int r = wid * 8 + ii;
        int grow = base_row + r;
        if (grow >= M) continue;          // uniform per warp
        float4 v = *reinterpret_cast<const float4*>(stg + r * 132 + lane * 4);
        v.x = fmaxf(v.x + b4.x, 0.f);
        v.y = fmaxf(v.y + b4.y, 0.f);
        v.z = fmaxf(v.z + b4.z, 0.f);
        v.w = fmaxf(v.w + b4.w, 0.f);
        float s  = v.x + v.y + v.z + v.w;
        float sq = v.x * v.x + v.y * v.y + v.z * v.z + v.w * v.w;
        #pragma unroll
        for (int o = 16; o > 0; o >>= 1) {
            s  += __shfl_xor_sync(0xFFFFFFFFu, s, o);
            sq += __shfl_xor_sync(0xFFFFFFFFu, sq, o);
        }
        float mean = s * (1.0f / DDIM);
        float var  = sq * (1.0f / DDIM) - mean * mean;
        float rstd = rsqrtf(var + 1e-5f);
        float4 o;
        o.x = (v.x - mean) * rstd * g4.x + t4.x;
        o.y = (v.y - mean) * rstd * g4.y + t4.y;
        o.z = (v.z - mean) * rstd * g4.z + t4.z;
        o.w = (v.w - mean) * rstd * g4.w + t4.w;
        *reinterpret_cast<float4*>(out + (size_t)grow * DDIM + lane * 4) = o;
    }
}

// ---------------------------------------------------------------------------
// Fully serial, single stream — no events, no statics.
// ---------------------------------------------------------------------------
extern "C" void kernel_launch(void* const* d_in, const int* in_sizes, int n_in,
                              void* d_out, int out_size)
{
    const float* x     = (const float*)d_in[0];
    const int*   ei    = (const int*)d_in[1];
    const float* aggW  = (const float*)d_in[2];
    const float* aggb  = (const float*)d_in[3];
    const float* W     = (const float*)d_in[4];
    const float* b     = (const float*)d_in[5];
    const float* gamma = (const float*)d_in[6];
    const float* beta  = (const float*)d_in[7];
    float* out = (float*)d_out;

    const int E = in_sizes[1] / 2;
    const int M = in_sizes[0] / DDIM;

    cudaFuncSetAttribute(mma_gemm_kernel,
                         cudaFuncAttributeMaxDynamicSharedMemorySize, SM_TOTAL);

    void* degi_p = nullptr;
    cudaGetSymbolAddress(&degi_p, g_degi);
    cudaMemsetAsync(degi_p, 0, (size_t)M * sizeof(int));

    const int* erow = ei;
    const int* ecol = ei + E;
    const int eb = (E + 255) / 256;

    hist_kernel<<<eb, 256>>>(ecol, E);
    scan_kernel<<<1, 1024>>>(M);
    binfill_kernel<<<eb, 256>>>(erow, ecol, E);
    gather_kernel<<<(M * 32 + 255) / 256, 256>>>(x, M);

    wcbc_kernel<<<128, 128>>>(aggW, aggb, W, b);
    prepB_kernel<<<128, 256>>>(W);

    mma_gemm_kernel<<<(M + 127) / 128, 512, SM_TOTAL>>>(x, gamma, beta, out, M);
}

// round 8
// speedup vs baseline: 2.0819x; 1.0374x over previous
#include <cuda_runtime.h>
#include <cuda_bf16.h>
#include <cstdint>

#define NMAX 50000
#define EMAX 800000
#define DDIM 128

// ---------------- static scratch (no allocation allowed) -------------------
__device__ float g_agg[(size_t)NMAX * DDIM];
__device__ float g_Wc[DDIM * DDIM];
__device__ float g_bc[DDIM];
__device__ int   g_degi[NMAX];
__device__ int   g_off[NMAX];
__device__ int   g_cur[NMAX];
__device__ int   g_bucket[EMAX];
__device__ __align__(16) short g_xq[(size_t)NMAX * DDIM];   // x quantized (x*2048)
// B = [W1 ; Wc]^T as bf16 hi/lo, layout [N=128][K=256] k-contiguous
__device__ __align__(16) __nv_bfloat16 g_Bh[128 * 256];
__device__ __align__(16) __nv_bfloat16 g_Bl[128 * 256];

#define XQ_SCALE 2048.0f
#define XQ_INV   (1.0f / 2048.0f)

// ---------------- K1: hist | wcbc | x-quantize (grid-section fusion) --------
__global__ __launch_bounds__(256) void k1_kernel(
    const int* __restrict__ ecol, int E, int eb,
    const float* __restrict__ aggW, const float* __restrict__ aggb,
    const float* __restrict__ W,    const float* __restrict__ b,
    const float* __restrict__ x, int nquad)   // nquad = M*DDIM/8 work items
{
    int bid = blockIdx.x;
    if (bid < eb) {
        // --- degree histogram ---
        int e = bid * 256 + threadIdx.x;
        if (e < E) atomicAdd(g_degi + ecol[e], 1);
    } else if (bid < eb + 64) {
        // --- fused weight Wc = aggW @ W2 (2 k-rows per block) + bc ---
        int k = (bid - eb) * 2 + (threadIdx.x >> 7);
        int n = threadIdx.x & 127;
        float acc = 0.f;
        #pragma unroll 8
        for (int j = 0; j < DDIM; j++)
            acc = fmaf(aggW[k * DDIM + j], W[(size_t)(DDIM + j) * DDIM + n], acc);
        g_Wc[k * DDIM + n] = acc;
        if (bid == eb && threadIdx.x < 128) {
            float bcv = b[n];
            #pragma unroll 8
            for (int j = 0; j < DDIM; j++)
                bcv = fmaf(aggb[j], W[(size_t)(DDIM + j) * DDIM + n], bcv);
            g_bc[n] = bcv;
        }
    } else {
        // --- quantize x -> int16 (8 elems per thread) ---
        int q = (bid - eb - 64) * 256 + threadIdx.x;
        if (q < nquad) {
            size_t base = (size_t)q * 8;
            float4 v0 = *reinterpret_cast<const float4*>(x + base);
            float4 v1 = *reinterpret_cast<const float4*>(x + base + 4);
            short o[8];
            o[0] = (short)max(-32767, min(32767, __float2int_rn(v0.x * XQ_SCALE)));
            o[1] = (short)max(-32767, min(32767, __float2int_rn(v0.y * XQ_SCALE)));
            o[2] = (short)max(-32767, min(32767, __float2int_rn(v0.z * XQ_SCALE)));
            o[3] = (short)max(-32767, min(32767, __float2int_rn(v0.w * XQ_SCALE)));
            o[4] = (short)max(-32767, min(32767, __float2int_rn(v1.x * XQ_SCALE)));
            o[5] = (short)max(-32767, min(32767, __float2int_rn(v1.y * XQ_SCALE)));
            o[6] = (short)max(-32767, min(32767, __float2int_rn(v1.z * XQ_SCALE)));
            o[7] = (short)max(-32767, min(32767, __float2int_rn(v1.w * XQ_SCALE)));
            *reinterpret_cast<uint4*>(g_xq + base) = *reinterpret_cast<uint4*>(o);
        }
    }
}

// ---------------- scan (single block, serial chunks + shfl) -----------------
__global__ __launch_bounds__(1024) void scan_kernel(int n)
{
    __shared__ int wsum[32];
    const int tid = threadIdx.x, lane = tid & 31, wid = tid >> 5;
    const int per = (n + 1023) / 1024;
    const int s0 = min(tid * per, n);
    const int s1 = min(s0 + per, n);
    int sum = 0;
    for (int i = s0; i < s1; i++) sum += g_degi[i];
    int v = sum;
    #pragma unroll
    for (int o = 1; o < 32; o <<= 1) {
        int t = __shfl_up_sync(0xFFFFFFFFu, v, o);
        if (lane >= o) v += t;
    }
    if (lane == 31) wsum[wid] = v;
    __syncthreads();
    if (wid == 0) {
        int w = wsum[lane];
        #pragma unroll
        for (int o = 1; o < 32; o <<= 1) {
            int t = __shfl_up_sync(0xFFFFFFFFu, w, o);
            if (lane >= o) w += t;
        }
        wsum[lane] = w;
    }
    __syncthreads();
    int run = v - sum + (wid ? wsum[wid - 1] : 0);
    for (int i = s0; i < s1; i++) {
        int d = g_degi[i];
        g_off[i] = run;
        g_cur[i] = run;
        run += d;
    }
}

// ---------------- K2: binfill | B transpose/split ---------------------------
__global__ __launch_bounds__(256) void k2_kernel(
    const int* __restrict__ erow, const int* __restrict__ ecol, int E, int eb,
    const float* __restrict__ W)
{
    int bid = blockIdx.x;
    if (bid < eb) {
        int e = bid * 256 + threadIdx.x;
        if (e >= E) return;
        int p = atomicAdd(g_cur + ecol[e], 1);
        g_bucket[p] = erow[e];
    } else {
        int idx = (bid - eb) * 256 + threadIdx.x;   // 0..32767
        if (idx >= 128 * 256) return;
        int n = idx >> 8, k = idx & 255;
        float v = (k < DDIM) ? W[(size_t)k * DDIM + n]
                             : g_Wc[(size_t)(k - DDIM) * DDIM + n];
        __nv_bfloat16 h = __float2bfloat16(v);
        __nv_bfloat16 l = __float2bfloat16(v - __bfloat162float(h));
        g_Bh[idx] = h;
        g_Bl[idx] = l;
    }
}

// ---------------- gather-mean from int16 (one warp per node, exact int32) ---
__global__ __launch_bounds__(256) void gather_kernel(int M)
{
    int w    = (blockIdx.x * blockDim.x + threadIdx.x) >> 5;
    int lane = threadIdx.x & 31;
    if (w >= M) return;
    int s = g_off[w];
    int d = g_degi[w];
    int a0 = 0, a1 = 0, a2 = 0, a3 = 0;
    int j = 0;
    for (; j + 4 <= d; j += 4) {
        int r0 = g_bucket[s + j + 0];
        int r1 = g_bucket[s + j + 1];
        int r2 = g_bucket[s + j + 2];
        int r3 = g_bucket[s + j + 3];
        uint2 w0 = *reinterpret_cast<const uint2*>(g_xq + (size_t)r0 * DDIM + lane * 4);
        uint2 w1 = *reinterpret_cast<const uint2*>(g_xq + (size_t)r1 * DDIM + lane * 4);
        uint2 w2 = *reinterpret_cast<const uint2*>(g_xq + (size_t)r2 * DDIM + lane * 4);
        uint2 w3 = *reinterpret_cast<const uint2*>(g_xq + (size_t)r3 * DDIM + lane * 4);
        a0 += (int)(short)(w0.x) + (int)(short)(w1.x) + (int)(short)(w2.x) + (int)(short)(w3.x);
        a1 += ((int)w0.x >> 16) + ((int)w1.x >> 16) + ((int)w2.x >> 16) + ((int)w3.x >> 16);
        a2 += (int)(short)(w0.y) + (int)(short)(w1.y) + (int)(short)(w2.y) + (int)(short)(w3.y);
        a3 += ((int)w0.y >> 16) + ((int)w1.y >> 16) + ((int)w2.y >> 16) + ((int)w3.y >> 16);
    }
    for (; j < d; j++) {
        int r = g_bucket[s + j];
        uint2 w0 = *reinterpret_cast<const uint2*>(g_xq + (size_t)r * DDIM + lane * 4);
        a0 += (int)(short)(w0.x);
        a1 += ((int)w0.x >> 16);
        a2 += (int)(short)(w0.y);
        a3 += ((int)w0.y >> 16);
    }
    float rd = XQ_INV / fmaxf((float)d, 1.0f);
    float4 o = make_float4((float)a0 * rd, (float)a1 * rd,
                           (float)a2 * rd, (float)a3 * rd);
    *reinterpret_cast<float4*>(g_agg + (size_t)w * DDIM + lane * 4) = o;
}

// ---------------- fused GEMM + ReLU + LayerNorm (R6-proven, unchanged) ------
#define A_STRIDE_B 272
#define B_STRIDE_B 528
#define SM_BIAS   0
#define SM_GAMMA  512
#define SM_BETA   1024
#define SM_AH     1536
#define SM_AL     (SM_AH + 128 * A_STRIDE_B)
#define SM_BH     (SM_AL + 128 * A_STRIDE_B)
#define SM_BL     (SM_BH + 128 * B_STRIDE_B)
#define SM_TOTAL  (SM_BL + 128 * B_STRIDE_B)    // 206336 B
#define SM_STAGE  SM_AH

__device__ __forceinline__ uint32_t smem_u32(const void* p) {
    uint32_t a;
    asm("{ .reg .u64 t; cvta.to.shared.u64 t, %1; cvt.u32.u64 %0, t; }"
        : "=r"(a) : "l"(p));
    return a;
}
__device__ __forceinline__ void ldmx4(uint32_t* r, uint32_t addr) {
    asm volatile("ldmatrix.sync.aligned.m8n8.x4.shared.b16 {%0,%1,%2,%3}, [%4];"
                 : "=r"(r[0]), "=r"(r[1]), "=r"(r[2]), "=r"(r[3]) : "r"(addr));
}
__device__ __forceinline__ void mma_bf16(float* c, const uint32_t* a, uint32_t b0, uint32_t b1) {
    asm volatile(
        "mma.sync.aligned.m16n8k16.row.col.f32.bf16.bf16.f32 "
        "{%0,%1,%2,%3}, {%4,%5,%6,%7}, {%8,%9}, {%0,%1,%2,%3};"
        : "+f"(c[0]), "+f"(c[1]), "+f"(c[2]), "+f"(c[3])
        : "r"(a[0]), "r"(a[1]), "r"(a[2]), "r"(a[3]), "r"(b0), "r"(b1));
}

__global__ __launch_bounds__(512, 1) void mma_gemm_kernel(
    const float* __restrict__ x,
    const float* __restrict__ gamma,
    const float* __restrict__ beta,
    float* __restrict__ out,
    int M)
{
    extern __shared__ char smem[];
    const uint32_t sb = smem_u32(smem);
    const int tid  = threadIdx.x;
    const int wid  = tid >> 5;
    const int lane = tid & 31;
    const int base_row = blockIdx.x * 128;
    const int warp_m = wid & 3;
    const int warp_n = wid >> 2;

    if (tid < 32) {
        reinterpret_cast<float4*>(smem + SM_BIAS)[tid]  =
            reinterpret_cast<const float4*>(g_bc)[tid];
        reinterpret_cast<float4*>(smem + SM_GAMMA)[tid] =
            reinterpret_cast<const float4*>(gamma)[tid];
        reinterpret_cast<float4*>(smem + SM_BETA)[tid]  =
            reinterpret_cast<const float4*>(beta)[tid];
    }
    #pragma unroll
    for (int i = 0; i < 8; i++) {
        int idx = tid + i * 512;
        int n = idx >> 5, q = idx & 31;
        *reinterpret_cast<uint4*>(smem + SM_BH + n * B_STRIDE_B + q * 16) =
            *reinterpret_cast<const uint4*>(g_Bh + n * 256 + q * 8);
        *reinterpret_cast<uint4*>(smem + SM_BL + n * B_STRIDE_B + q * 16) =
            *reinterpret_cast<const uint4*>(g_Bl + n * 256 + q * 8);
    }

    auto fill_half = [&](const float* __restrict__ src) {
        #pragma unroll
        for (int i = 0; i < 8; i++) {
            int idx = tid + i * 512;
            int row = idx >> 5;
            int kq  = (idx & 31) * 4;
            int grow = base_row + row;
            if (grow >= M) grow = M - 1;
            float4 v = *reinterpret_cast<const float4*>(src + (size_t)grow * DDIM + kq);
            __nv_bfloat16 h0 = __float2bfloat16(v.x);
            __nv_bfloat16 h1 = __float2bfloat16(v.y);
            __nv_bfloat16 h2 = __float2bfloat16(v.z);
            __nv_bfloat16 h3 = __float2bfloat16(v.w);
            __nv_bfloat16 l0 = __float2bfloat16(v.x - __bfloat162float(h0));
            __nv_bfloat16 l1 = __float2bfloat16(v.y - __bfloat162float(h1));
            __nv_bfloat16 l2 = __float2bfloat16(v.z - __bfloat162float(h2));
            __nv_bfloat16 l3 = __float2bfloat16(v.w - __bfloat162float(h3));
            uint2 hw, lw;
            hw.x = ((uint32_t)__bfloat16_as_ushort(h1) << 16) | __bfloat16_as_ushort(h0);
            hw.y = ((uint32_t)__bfloat16_as_ushort(h3) << 16) | __bfloat16_as_ushort(h2);
            lw.x = ((uint32_t)__bfloat16_as_ushort(l1) << 16) | __bfloat16_as_ushort(l0);
            lw.y = ((uint32_t)__bfloat16_as_ushort(l3) << 16) | __bfloat16_as_ushort(l2);
            uint32_t off = (uint32_t)row * A_STRIDE_B + (uint32_t)kq * 2;
            *reinterpret_cast<uint2*>(smem + SM_AH + off) = hw;
            *reinterpret_cast<uint2*>(smem + SM_AL + off) = lw;
        }
    };

    float acc[2][4][4];
    #pragma unroll
    for (int i = 0; i < 2; i++)
        #pragma unroll
        for (int j = 0; j < 4; j++)
            #pragma unroll
            for (int c = 0; c < 4; c++) acc[i][j][c] = 0.f;

    const int a_row_lo = (lane & 7) + ((lane >> 3) & 1) * 8;
    const int a_koff   = ((lane >> 4) & 1) * 8;
    const int b_nrow   = warp_n * 32 + (lane & 7) + ((lane >> 4) & 1) * 8;
    const int b_koff   = ((lane >> 3) & 1) * 8;

    auto compute_half = [&](int h) {
        #pragma unroll
        for (int kc = 0; kc < 8; kc++) {
            const int kA = kc * 16 + a_koff;
            const int kB = h * 128 + kc * 16 + b_koff;
            uint32_t ah[2][4], al[2][4];
            #pragma unroll
            for (int i = 0; i < 2; i++) {
                int row = warp_m * 32 + i * 16 + a_row_lo;
                uint32_t off = (uint32_t)row * A_STRIDE_B + (uint32_t)kA * 2;
                ldmx4(ah[i], sb + SM_AH + off);
                ldmx4(al[i], sb + SM_AL + off);
            }
            uint32_t bh[2][4], bl[2][4];
            #pragma unroll
            for (int p = 0; p < 2; p++) {
                uint32_t off = (uint32_t)(b_nrow + p * 16) * B_STRIDE_B + (uint32_t)kB * 2;
                ldmx4(bh[p], sb + SM_BH + off);
                ldmx4(bl[p], sb + SM_BL + off);
            }
            #pragma unroll
            for (int i = 0; i < 2; i++)
                #pragma unroll
                for (int p = 0; p < 2; p++) {
                    mma_bf16(acc[i][2 * p],     ah[i], bh[p][0], bh[p][1]);
                    mma_bf16(acc[i][2 * p + 1], ah[i], bh[p][2], bh[p][3]);
                    mma_bf16(acc[i][2 * p],     ah[i], bl[p][0], bl[p][1]);
                    mma_bf16(acc[i][2 * p + 1], ah[i], bl[p][2], bl[p][3]);
                    mma_bf16(acc[i][2 * p],     al[i], bh[p][0], bh[p][1]);
                    mma_bf16(acc[i][2 * p + 1], al[i], bh[p][2], bh[p][3]);
                }
        }
    };

    fill_half(x);
    __syncthreads();
    compute_half(0);
    __syncthreads();
    fill_half(g_agg);
    __syncthreads();
    compute_half(1);
    __syncthreads();

    float* stg = reinterpret_cast<float*>(smem + SM_STAGE);
    #pragma unroll
    for (int i = 0; i < 2; i++) {
        int row0 = warp_m * 32 + i * 16 + (lane >> 2);
        #pragma unroll
        for (int j = 0; j < 4; j++) {
            int col = warp_n * 32 + j * 8 + (lane & 3) * 2;
            *reinterpret_cast<float2*>(stg + row0 * 132 + col) =
                make_float2(acc[i][j][0], acc[i][j][1]);
            *reinterpret_cast<float2*>(stg + (row0 + 8) * 132 + col) =
                make_float2(acc[i][j][2], acc[i][j][3]);
        }
    }
    __syncthreads();

    float4 b4 = *reinterpret_cast<const float4*>(smem + SM_BIAS  + lane * 16);
    float4 g4 = *reinterpret_cast<const float4*>(smem + SM_GAMMA + lane * 16);
    float4 t4 = *reinterpret_cast<const float4*>(smem + SM_BETA  + lane * 16);
    #pragma unroll
    for (int ii = 0; ii < 8; ii++) {
        int r = wid * 8 + ii;
        int grow = base_row + r;
        if (grow >= M) continue;
        float4 v = *reinterpret_cast<const float4*>(stg + r * 132 + lane * 4);
        v.x = fmaxf(v.x + b4.x, 0.f);
        v.y = fmaxf(v.y + b4.y, 0.f);
        v.z = fmaxf(v.z + b4.z, 0.f);
        v.w = fmaxf(v.w + b4.w, 0.f);
        float s  = v.x + v.y + v.z + v.w;
        float sq = v.x * v.x + v.y * v.y + v.z * v.z + v.w * v.w;
        #pragma unroll
        for (int o = 16; o > 0; o >>= 1) {
            s  += __shfl_xor_sync(0xFFFFFFFFu, s, o);
            sq += __shfl_xor_sync(0xFFFFFFFFu, sq, o);
        }
        float mean = s * (1.0f / DDIM);
        float var  = sq * (1.0f / DDIM) - mean * mean;
        float rstd = rsqrtf(var + 1e-5f);
        float4 o;
        o.x = (v.x - mean) * rstd * g4.x + t4.x;
        o.y = (v.y - mean) * rstd * g4.y + t4.y;
        o.z = (v.z - mean) * rstd * g4.z + t4.z;
        o.w = (v.w - mean) * rstd * g4.w + t4.w;
        *reinterpret_cast<float4*>(out + (size_t)grow * DDIM + lane * 4) = o;
    }
}

// ---------------------------------------------------------------------------
// Single stream, serial. Independent small work rides inside big launches.
// ---------------------------------------------------------------------------
extern "C" void kernel_launch(void* const* d_in, const int* in_sizes, int n_in,
                              void* d_out, int out_size)
{
    const float* x     = (const float*)d_in[0];
    const int*   ei    = (const int*)d_in[1];
    const float* aggW  = (const float*)d_in[2];
    const float* aggb  = (const float*)d_in[3];
    const float* W     = (const float*)d_in[4];
    const float* b     = (const float*)d_in[5];
    const float* gamma = (const float*)d_in[6];
    const float* beta  = (const float*)d_in[7];
    float* out = (float*)d_out;

    const int E = in_sizes[1] / 2;
    const int M = in_sizes[0] / DDIM;

    cudaFuncSetAttribute(mma_gemm_kernel,
                         cudaFuncAttributeMaxDynamicSharedMemorySize, SM_TOTAL);

    void* degi_p = nullptr;
    cudaGetSymbolAddress(&degi_p, g_degi);
    cudaMemsetAsync(degi_p, 0, (size_t)M * sizeof(int));

    const int* erow = ei;
    const int* ecol = ei + E;
    const int eb = (E + 255) / 256;                  // hist / binfill blocks
    const int nquad = (M * DDIM) / 8;                // 8 elems per thread
    const int pb = (nquad + 255) / 256;              // quantize blocks
    const int bb = (128 * 256 + 255) / 256;          // prepB blocks

    k1_kernel<<<eb + 64 + pb, 256>>>(ecol, E, eb, aggW, aggb, W, b, x, nquad);
    scan_kernel<<<1, 1024>>>(M);
    k2_kernel<<<eb + bb, 256>>>(erow, ecol, E, eb, W);
    gather_kernel<<<(M * 32 + 255) / 256, 256>>>(M);
    mma_gemm_kernel<<<(M + 127) / 128, 512, SM_TOTAL>>>(x, gamma, beta, out, M);
}

// round 9
// speedup vs baseline: 2.2280x; 1.0702x over previous
#include <cuda_runtime.h>
#include <cuda_fp16.h>
#include <cstdint>

#define NMAX 50000
#define EMAX 800000
#define DDIM 128

// ---------------- static scratch (no allocation allowed) -------------------
__device__ float g_agg[(size_t)NMAX * DDIM];
__device__ float g_Wc[DDIM * DDIM];
__device__ float g_bc[DDIM];
__device__ int   g_degi[NMAX];       // zero-invariant: gather re-zeroes after use
__device__ int   g_off[NMAX];
__device__ int   g_cur[NMAX];
__device__ int   g_bucket[EMAX];
__device__ __align__(16) short g_xq[(size_t)NMAX * DDIM];   // x*2048 int16
// B = [W1 ; Wc]^T as fp16, layout [N=128][K=256] k-contiguous
__device__ __align__(16) __half g_Bf[128 * 256];

#define XQ_SCALE 2048.0f
#define XQ_INV   (1.0f / 2048.0f)

// ---------------- K1: hist | wcbc | x-quantize (grid-section fusion) --------
__global__ __launch_bounds__(256) void k1_kernel(
    const int* __restrict__ ecol, int E, int eb,
    const float* __restrict__ aggW, const float* __restrict__ aggb,
    const float* __restrict__ W,    const float* __restrict__ b,
    const float* __restrict__ x, int nquad)
{
    int bid = blockIdx.x;
    if (bid < eb) {
        int e = bid * 256 + threadIdx.x;
        if (e < E) atomicAdd(g_degi + ecol[e], 1);
    } else if (bid < eb + 64) {
        int k = (bid - eb) * 2 + (threadIdx.x >> 7);
        int n = threadIdx.x & 127;
        float acc = 0.f;
        #pragma unroll 8
        for (int j = 0; j < DDIM; j++)
            acc = fmaf(aggW[k * DDIM + j], W[(size_t)(DDIM + j) * DDIM + n], acc);
        g_Wc[k * DDIM + n] = acc;
        if (bid == eb && threadIdx.x < 128) {
            float bcv = b[n];
            #pragma unroll 8
            for (int j = 0; j < DDIM; j++)
                bcv = fmaf(aggb[j], W[(size_t)(DDIM + j) * DDIM + n], bcv);
            g_bc[n] = bcv;
        }
    } else {
        int q = (bid - eb - 64) * 256 + threadIdx.x;
        if (q < nquad) {
            size_t base = (size_t)q * 8;
            float4 v0 = *reinterpret_cast<const float4*>(x + base);
            float4 v1 = *reinterpret_cast<const float4*>(x + base + 4);
            short o[8];
            o[0] = (short)max(-32767, min(32767, __float2int_rn(v0.x * XQ_SCALE)));
            o[1] = (short)max(-32767, min(32767, __float2int_rn(v0.y * XQ_SCALE)));
            o[2] = (short)max(-32767, min(32767, __float2int_rn(v0.z * XQ_SCALE)));
            o[3] = (short)max(-32767, min(32767, __float2int_rn(v0.w * XQ_SCALE)));
            o[4] = (short)max(-32767, min(32767, __float2int_rn(v1.x * XQ_SCALE)));
            o[5] = (short)max(-32767, min(32767, __float2int_rn(v1.y * XQ_SCALE)));
            o[6] = (short)max(-32767, min(32767, __float2int_rn(v1.z * XQ_SCALE)));
            o[7] = (short)max(-32767, min(32767, __float2int_rn(v1.w * XQ_SCALE)));
            *reinterpret_cast<uint4*>(g_xq + base) = *reinterpret_cast<uint4*>(o);
        }
    }
}

// ---------------- scan (single block, serial chunks + shfl) -----------------
__global__ __launch_bounds__(1024) void scan_kernel(int n)
{
    __shared__ int wsum[32];
    const int tid = threadIdx.x, lane = tid & 31, wid = tid >> 5;
    const int per = (n + 1023) / 1024;
    const int s0 = min(tid * per, n);
    const int s1 = min(s0 + per, n);
    int sum = 0;
    for (int i = s0; i < s1; i++) sum += g_degi[i];
    int v = sum;
    #pragma unroll
    for (int o = 1; o < 32; o <<= 1) {
        int t = __shfl_up_sync(0xFFFFFFFFu, v, o);
        if (lane >= o) v += t;
    }
    if (lane == 31) wsum[wid] = v;
    __syncthreads();
    if (wid == 0) {
        int w = wsum[lane];
        #pragma unroll
        for (int o = 1; o < 32; o <<= 1) {
            int t = __shfl_up_sync(0xFFFFFFFFu, w, o);
            if (lane >= o) w += t;
        }
        wsum[lane] = w;
    }
    __syncthreads();
    int run = v - sum + (wid ? wsum[wid - 1] : 0);
    for (int i = s0; i < s1; i++) {
        int d = g_degi[i];
        g_off[i] = run;
        g_cur[i] = run;
        run += d;
    }
}

// ---------------- K2: binfill | B transpose + fp16 convert ------------------
__global__ __launch_bounds__(256) void k2_kernel(
    const int* __restrict__ erow, const int* __restrict__ ecol, int E, int eb,
    const float* __restrict__ W)
{
    int bid = blockIdx.x;
    if (bid < eb) {
        int e = bid * 256 + threadIdx.x;
        if (e >= E) return;
        int p = atomicAdd(g_cur + ecol[e], 1);
        g_bucket[p] = erow[e];
    } else {
        int idx = (bid - eb) * 256 + threadIdx.x;
        if (idx >= 128 * 256) return;
        int n = idx >> 8, k = idx & 255;
        float v = (k < DDIM) ? W[(size_t)k * DDIM + n]
                             : g_Wc[(size_t)(k - DDIM) * DDIM + n];
        g_Bf[idx] = __float2half_rn(v);
    }
}

// ---------------- gather-mean from int16 + g_degi self-clear ----------------
__global__ __launch_bounds__(256) void gather_kernel(int M)
{
    int w    = (blockIdx.x * blockDim.x + threadIdx.x) >> 5;
    int lane = threadIdx.x & 31;
    if (w >= M) return;
    int s = g_off[w];
    int d = g_degi[w];
    int a0 = 0, a1 = 0, a2 = 0, a3 = 0;
    int j = 0;
    for (; j + 4 <= d; j += 4) {
        int r0 = g_bucket[s + j + 0];
        int r1 = g_bucket[s + j + 1];
        int r2 = g_bucket[s + j + 2];
        int r3 = g_bucket[s + j + 3];
        uint2 w0 = *reinterpret_cast<const uint2*>(g_xq + (size_t)r0 * DDIM + lane * 4);
        uint2 w1 = *reinterpret_cast<const uint2*>(g_xq + (size_t)r1 * DDIM + lane * 4);
        uint2 w2 = *reinterpret_cast<const uint2*>(g_xq + (size_t)r2 * DDIM + lane * 4);
        uint2 w3 = *reinterpret_cast<const uint2*>(g_xq + (size_t)r3 * DDIM + lane * 4);
        a0 += (int)(short)(w0.x) + (int)(short)(w1.x) + (int)(short)(w2.x) + (int)(short)(w3.x);
        a1 += ((int)w0.x >> 16) + ((int)w1.x >> 16) + ((int)w2.x >> 16) + ((int)w3.x >> 16);
        a2 += (int)(short)(w0.y) + (int)(short)(w1.y) + (int)(short)(w2.y) + (int)(short)(w3.y);
        a3 += ((int)w0.y >> 16) + ((int)w1.y >> 16) + ((int)w2.y >> 16) + ((int)w3.y >> 16);
    }
    for (; j < d; j++) {
        int r = g_bucket[s + j];
        uint2 w0 = *reinterpret_cast<const uint2*>(g_xq + (size_t)r * DDIM + lane * 4);
        a0 += (int)(short)(w0.x);
        a1 += ((int)w0.x >> 16);
        a2 += (int)(short)(w0.y);
        a3 += ((int)w0.y >> 16);
    }
    float rd = XQ_INV / fmaxf((float)d, 1.0f);
    float4 o = make_float4((float)a0 * rd, (float)a1 * rd,
                           (float)a2 * rd, (float)a3 * rd);
    *reinterpret_cast<float4*>(g_agg + (size_t)w * DDIM + lane * 4) = o;
    if (lane == 0) g_degi[w] = 0;      // restore zero-invariant for next call
}

// ---------------- fused GEMM + ReLU + LayerNorm (fp16 2-pass) ---------------
// out = LN(relu(x @ W1 + agg @ Wc + bc)) * gamma + beta
// A split Ah+Al (fp16); B single fp16 image. acc = (Ah+Al) @ B, fp32 accum.
#define A_STRIDE_B 272          // 128 fp16 + 16B pad
#define B_STRIDE_B 528          // 256 fp16 + 16B pad
#define SM_BIAS   0
#define SM_GAMMA  512
#define SM_BETA   1024
#define SM_AH     1536
#define SM_AL     (SM_AH + 128 * A_STRIDE_B)        // 36352
#define SM_BF     (SM_AL + 128 * A_STRIDE_B)        // 71168
#define SM_TOTAL  (SM_BF + 128 * B_STRIDE_B)        // 138752 B
#define SM_STAGE  SM_AH                              // 128*132*4 = 67584 B

__device__ __forceinline__ uint32_t smem_u32(const void* p) {
    uint32_t a;
    asm("{ .reg .u64 t; cvta.to.shared.u64 t, %1; cvt.u32.u64 %0, t; }"
        : "=r"(a) : "l"(p));
    return a;
}
__device__ __forceinline__ void ldmx4(uint32_t* r, uint32_t addr) {
    asm volatile("ldmatrix.sync.aligned.m8n8.x4.shared.b16 {%0,%1,%2,%3}, [%4];"
                 : "=r"(r[0]), "=r"(r[1]), "=r"(r[2]), "=r"(r[3]) : "r"(addr));
}
__device__ __forceinline__ void mma_f16(float* c, const uint32_t* a, uint32_t b0, uint32_t b1) {
    asm volatile(
        "mma.sync.aligned.m16n8k16.row.col.f32.f16.f16.f32 "
        "{%0,%1,%2,%3}, {%4,%5,%6,%7}, {%8,%9}, {%0,%1,%2,%3};"
        : "+f"(c[0]), "+f"(c[1]), "+f"(c[2]), "+f"(c[3])
        : "r"(a[0]), "r"(a[1]), "r"(a[2]), "r"(a[3]), "r"(b0), "r"(b1));
}

__global__ __launch_bounds__(512, 1) void mma_gemm_kernel(
    const float* __restrict__ x,
    const float* __restrict__ gamma,
    const float* __restrict__ beta,
    float* __restrict__ out,
    int M)
{
    extern __shared__ char smem[];
    const uint32_t sb = smem_u32(smem);
    const int tid  = threadIdx.x;
    const int wid  = tid >> 5;
    const int lane = tid & 31;
    const int base_row = blockIdx.x * 128;
    const int warp_m = wid & 3;
    const int warp_n = wid >> 2;

    if (tid < 32) {
        reinterpret_cast<float4*>(smem + SM_BIAS)[tid]  =
            reinterpret_cast<const float4*>(g_bc)[tid];
        reinterpret_cast<float4*>(smem + SM_GAMMA)[tid] =
            reinterpret_cast<const float4*>(gamma)[tid];
        reinterpret_cast<float4*>(smem + SM_BETA)[tid]  =
            reinterpret_cast<const float4*>(beta)[tid];
    }
    // B fp16 -> smem: 128 rows x 512B
    #pragma unroll
    for (int i = 0; i < 8; i++) {
        int idx = tid + i * 512;            // 0..4095 uint4
        int n = idx >> 5, q = idx & 31;
        *reinterpret_cast<uint4*>(smem + SM_BF + n * B_STRIDE_B + q * 16) =
            *reinterpret_cast<const uint4*>(g_Bf + n * 256 + q * 8);
    }

    // per-thread A source coords
    const int arow = tid >> 2;                       // wait—needs 128 rows x 32 q
    // (use idx mapping inside loops instead)

    // convert float4 -> fp16 hi/lo packed and store to A images
    auto cvt_store = [&](float4 v, int row, int kq) {
        __half h0 = __float2half_rn(v.x);
        __half h1 = __float2half_rn(v.y);
        __half h2 = __float2half_rn(v.z);
        __half h3 = __float2half_rn(v.w);
        __half l0 = __float2half_rn(v.x - __half2float(h0));
        __half l1 = __float2half_rn(v.y - __half2float(h1));
        __half l2 = __float2half_rn(v.z - __half2float(h2));
        __half l3 = __float2half_rn(v.w - __half2float(h3));
        uint2 hw, lw;
        hw.x = ((uint32_t)__half_as_ushort(h1) << 16) | __half_as_ushort(h0);
        hw.y = ((uint32_t)__half_as_ushort(h3) << 16) | __half_as_ushort(h2);
        lw.x = ((uint32_t)__half_as_ushort(l1) << 16) | __half_as_ushort(l0);
        lw.y = ((uint32_t)__half_as_ushort(l3) << 16) | __half_as_ushort(l2);
        uint32_t off = (uint32_t)row * A_STRIDE_B + (uint32_t)kq * 2;
        *reinterpret_cast<uint2*>(smem + SM_AH + off) = hw;
        *reinterpret_cast<uint2*>(smem + SM_AL + off) = lw;
    };

    // fill x half
    #pragma unroll
    for (int i = 0; i < 8; i++) {
        int idx = tid + i * 512;
        int row = idx >> 5;
        int kq  = (idx & 31) * 4;
        int grow = base_row + row;
        if (grow >= M) grow = M - 1;
        cvt_store(*reinterpret_cast<const float4*>(x + (size_t)grow * DDIM + kq), row, kq);
    }
    __syncthreads();

    // prefetch agg half into registers (hidden behind compute of x half)
    float4 pre[8];
    #pragma unroll
    for (int i = 0; i < 8; i++) {
        int idx = tid + i * 512;
        int row = idx >> 5;
        int kq  = (idx & 31) * 4;
        int grow = base_row + row;
        if (grow >= M) grow = M - 1;
        pre[i] = *reinterpret_cast<const float4*>(g_agg + (size_t)grow * DDIM + kq);
    }

    float acc[2][4][4];
    #pragma unroll
    for (int i = 0; i < 2; i++)
        #pragma unroll
        for (int j = 0; j < 4; j++)
            #pragma unroll
            for (int c = 0; c < 4; c++) acc[i][j][c] = 0.f;

    const int a_row_lo = (lane & 7) + ((lane >> 3) & 1) * 8;
    const int a_koff   = ((lane >> 4) & 1) * 8;
    const int b_nrow   = warp_n * 32 + (lane & 7) + ((lane >> 4) & 1) * 8;
    const int b_koff   = ((lane >> 3) & 1) * 8;

    auto compute_half = [&](int h) {
        #pragma unroll
        for (int kc = 0; kc < 8; kc++) {
            const int kA = kc * 16 + a_koff;
            const int kB = h * 128 + kc * 16 + b_koff;
            uint32_t ah[2][4], al[2][4];
            #pragma unroll
            for (int i = 0; i < 2; i++) {
                int row = warp_m * 32 + i * 16 + a_row_lo;
                uint32_t off = (uint32_t)row * A_STRIDE_B + (uint32_t)kA * 2;
                ldmx4(ah[i], sb + SM_AH + off);
                ldmx4(al[i], sb + SM_AL + off);
            }
            uint32_t bf[2][4];
            #pragma unroll
            for (int p = 0; p < 2; p++) {
                uint32_t off = (uint32_t)(b_nrow + p * 16) * B_STRIDE_B + (uint32_t)kB * 2;
                ldmx4(bf[p], sb + SM_BF + off);
            }
            #pragma unroll
            for (int i = 0; i < 2; i++)
                #pragma unroll
                for (int p = 0; p < 2; p++) {
                    mma_f16(acc[i][2 * p],     ah[i], bf[p][0], bf[p][1]);
                    mma_f16(acc[i][2 * p + 1], ah[i], bf[p][2], bf[p][3]);
                    mma_f16(acc[i][2 * p],     al[i], bf[p][0], bf[p][1]);
                    mma_f16(acc[i][2 * p + 1], al[i], bf[p][2], bf[p][3]);
                }
        }
    };

    compute_half(0);
    __syncthreads();            // all warps done reading x images

    // store prefetched agg half
    #pragma unroll
    for (int i = 0; i < 8; i++) {
        int idx = tid + i * 512;
        int row = idx >> 5;
        int kq  = (idx & 31) * 4;
        cvt_store(pre[i], row, kq);
    }
    __syncthreads();
    compute_half(1);
    __syncthreads();

    // stage accumulators [128][132] (reuses A region)
    float* stg = reinterpret_cast<float*>(smem + SM_STAGE);
    #pragma unroll
    for (int i = 0; i < 2; i++) {
        int row0 = warp_m * 32 + i * 16 + (lane >> 2);
        #pragma unroll
        for (int j = 0; j < 4; j++) {
            int col = warp_n * 32 + j * 8 + (lane & 3) * 2;
            *reinterpret_cast<float2*>(stg + row0 * 132 + col) =
                make_float2(acc[i][j][0], acc[i][j][1]);
            *reinterpret_cast<float2*>(stg + (row0 + 8) * 132 + col) =
                make_float2(acc[i][j][2], acc[i][j][3]);
        }
    }
    __syncthreads();

    float4 b4 = *reinterpret_cast<const float4*>(smem + SM_BIAS  + lane * 16);
    float4 g4 = *reinterpret_cast<const float4*>(smem + SM_GAMMA + lane * 16);
    float4 t4 = *reinterpret_cast<const float4*>(smem + SM_BETA  + lane * 16);
    #pragma unroll
    for (int ii = 0; ii < 8; ii++) {
        int r = wid * 8 + ii;
        int grow = base_row + r;
        if (grow >= M) continue;
        float4 v = *reinterpret_cast<const float4*>(stg + r * 132 + lane * 4);
        v.x = fmaxf(v.x + b4.x, 0.f);
        v.y = fmaxf(v.y + b4.y, 0.f);
        v.z = fmaxf(v.z + b4.z, 0.f);
        v.w = fmaxf(v.w + b4.w, 0.f);
        float s  = v.x + v.y + v.z + v.w;
        float sq = v.x * v.x + v.y * v.y + v.z * v.z + v.w * v.w;
        #pragma unroll
        for (int o = 16; o > 0; o >>= 1) {
            s  += __shfl_xor_sync(0xFFFFFFFFu, s, o);
            sq += __shfl_xor_sync(0xFFFFFFFFu, sq, o);
        }
        float mean = s * (1.0f / DDIM);
        float var  = sq * (1.0f / DDIM) - mean * mean;
        float rstd = rsqrtf(var + 1e-5f);
        float4 o;
        o.x = (v.x - mean) * rstd * g4.x + t4.x;
        o.y = (v.y - mean) * rstd * g4.y + t4.y;
        o.z = (v.z - mean) * rstd * g4.z + t4.z;
        o.w = (v.w - mean) * rstd * g4.w + t4.w;
        *reinterpret_cast<float4*>(out + (size_t)grow * DDIM + lane * 4) = o;
    }
}

// ---------------------------------------------------------------------------
extern "C" void kernel_launch(void* const* d_in, const int* in_sizes, int n_in,
                              void* d_out, int out_size)
{
    const float* x     = (const float*)d_in[0];
    const int*   ei    = (const int*)d_in[1];
    const float* aggW  = (const float*)d_in[2];
    const float* aggb  = (const float*)d_in[3];
    const float* W     = (const float*)d_in[4];
    const float* b     = (const float*)d_in[5];
    const float* gamma = (const float*)d_in[6];
    const float* beta  = (const float*)d_in[7];
    float* out = (float*)d_out;

    const int E = in_sizes[1] / 2;
    const int M = in_sizes[0] / DDIM;

    cudaFuncSetAttribute(mma_gemm_kernel,
                         cudaFuncAttributeMaxDynamicSharedMemorySize, SM_TOTAL);

    const int* erow = ei;
    const int* ecol = ei + E;
    const int eb = (E + 255) / 256;
    const int nquad = (M * DDIM) / 8;
    const int pb = (nquad + 255) / 256;
    const int bb = (128 * 256 + 255) / 256;

    k1_kernel<<<eb + 64 + pb, 256>>>(ecol, E, eb, aggW, aggb, W, b, x, nquad);
    scan_kernel<<<1, 1024>>>(M);
    k2_kernel<<<eb + bb, 256>>>(erow, ecol, E, eb, W);
    gather_kernel<<<(M * 32 + 255) / 256, 256>>>(M);
    mma_gemm_kernel<<<(M + 127) / 128, 512, SM_TOTAL>>>(x, gamma, beta, out, M);
}

// round 10
// speedup vs baseline: 2.2557x; 1.0124x over previous
#include <cuda_runtime.h>
#include <cuda_fp16.h>
#include <cstdint>

#define NMAX 50000
#define EMAX 800000
#define DDIM 128

// ---------------- static scratch (no allocation allowed) -------------------
__device__ float g_agg[(size_t)NMAX * DDIM];
__device__ float g_Wc[DDIM * DDIM];
__device__ float g_bc[DDIM];
__device__ int   g_degi[NMAX];       // zero-invariant: gather re-zeroes after use
__device__ int   g_off[NMAX];
__device__ int   g_cur[NMAX];
__device__ int   g_bucket[EMAX];
__device__ __align__(16) short g_xq[(size_t)NMAX * DDIM];   // x*2048 int16
// B = [W1 ; Wc]^T as fp16, layout [N=128][K=256] k-contiguous
__device__ __align__(16) __half g_Bf[128 * 256];

#define XQ_SCALE 2048.0f
#define XQ_INV   (1.0f / 2048.0f)

// ---------------- K1: hist | wcbc | x-quantize (grid-section fusion) --------
__global__ __launch_bounds__(256) void k1_kernel(
    const int* __restrict__ ecol, int E, int eb,
    const float* __restrict__ aggW, const float* __restrict__ aggb,
    const float* __restrict__ W,    const float* __restrict__ b,
    const float* __restrict__ x, int nquad)
{
    int bid = blockIdx.x;
    if (bid < eb) {
        int e = bid * 256 + threadIdx.x;
        if (e < E) atomicAdd(g_degi + ecol[e], 1);
    } else if (bid < eb + 64) {
        int k = (bid - eb) * 2 + (threadIdx.x >> 7);
        int n = threadIdx.x & 127;
        float acc = 0.f;
        #pragma unroll 8
        for (int j = 0; j < DDIM; j++)
            acc = fmaf(aggW[k * DDIM + j], W[(size_t)(DDIM + j) * DDIM + n], acc);
        g_Wc[k * DDIM + n] = acc;
        if (bid == eb && threadIdx.x < 128) {
            float bcv = b[n];
            #pragma unroll 8
            for (int j = 0; j < DDIM; j++)
                bcv = fmaf(aggb[j], W[(size_t)(DDIM + j) * DDIM + n], bcv);
            g_bc[n] = bcv;
        }
    } else {
        int q = (bid - eb - 64) * 256 + threadIdx.x;
        if (q < nquad) {
            size_t base = (size_t)q * 8;
            float4 v0 = *reinterpret_cast<const float4*>(x + base);
            float4 v1 = *reinterpret_cast<const float4*>(x + base + 4);
            short o[8];
            o[0] = (short)max(-32767, min(32767, __float2int_rn(v0.x * XQ_SCALE)));
            o[1] = (short)max(-32767, min(32767, __float2int_rn(v0.y * XQ_SCALE)));
            o[2] = (short)max(-32767, min(32767, __float2int_rn(v0.z * XQ_SCALE)));
            o[3] = (short)max(-32767, min(32767, __float2int_rn(v0.w * XQ_SCALE)));
            o[4] = (short)max(-32767, min(32767, __float2int_rn(v1.x * XQ_SCALE)));
            o[5] = (short)max(-32767, min(32767, __float2int_rn(v1.y * XQ_SCALE)));
            o[6] = (short)max(-32767, min(32767, __float2int_rn(v1.z * XQ_SCALE)));
            o[7] = (short)max(-32767, min(32767, __float2int_rn(v1.w * XQ_SCALE)));
            *reinterpret_cast<uint4*>(g_xq + base) = *reinterpret_cast<uint4*>(o);
        }
    }
}

// ---------------- scan (single block, serial chunks + shfl) -----------------
__global__ __launch_bounds__(1024) void scan_kernel(int n)
{
    __shared__ int wsum[32];
    const int tid = threadIdx.x, lane = tid & 31, wid = tid >> 5;
    const int per = (n + 1023) / 1024;
    const int s0 = min(tid * per, n);
    const int s1 = min(s0 + per, n);
    int sum = 0;
    for (int i = s0; i < s1; i++) sum += g_degi[i];
    int v = sum;
    #pragma unroll
    for (int o = 1; o < 32; o <<= 1) {
        int t = __shfl_up_sync(0xFFFFFFFFu, v, o);
        if (lane >= o) v += t;
    }
    if (lane == 31) wsum[wid] = v;
    __syncthreads();
    if (wid == 0) {
        int w = wsum[lane];
        #pragma unroll
        for (int o = 1; o < 32; o <<= 1) {
            int t = __shfl_up_sync(0xFFFFFFFFu, w, o);
            if (lane >= o) w += t;
        }
        wsum[lane] = w;
    }
    __syncthreads();
    int run = v - sum + (wid ? wsum[wid - 1] : 0);
    for (int i = s0; i < s1; i++) {
        int d = g_degi[i];
        g_off[i] = run;
        g_cur[i] = run;
        run += d;
    }
}

// ---------------- K2: binfill | B transpose + fp16 convert ------------------
__global__ __launch_bounds__(256) void k2_kernel(
    const int* __restrict__ erow, const int* __restrict__ ecol, int E, int eb,
    const float* __restrict__ W)
{
    int bid = blockIdx.x;
    if (bid < eb) {
        int e = bid * 256 + threadIdx.x;
        if (e >= E) return;
        int p = atomicAdd(g_cur + ecol[e], 1);
        g_bucket[p] = erow[e];
    } else {
        int idx = (bid - eb) * 256 + threadIdx.x;
        if (idx >= 128 * 256) return;
        int n = idx >> 8, k = idx & 255;
        float v = (k < DDIM) ? W[(size_t)k * DDIM + n]
                             : g_Wc[(size_t)(k - DDIM) * DDIM + n];
        g_Bf[idx] = __float2half_rn(v);
    }
}

// ---------------- gather-mean from int16 + g_degi self-clear ----------------
__global__ __launch_bounds__(256) void gather_kernel(int M)
{
    int w    = (blockIdx.x * blockDim.x + threadIdx.x) >> 5;
    int lane = threadIdx.x & 31;
    if (w >= M) return;
    int s = g_off[w];
    int d = g_degi[w];
    int a0 = 0, a1 = 0, a2 = 0, a3 = 0;
    int j = 0;
    for (; j + 4 <= d; j += 4) {
        int r0 = g_bucket[s + j + 0];
        int r1 = g_bucket[s + j + 1];
        int r2 = g_bucket[s + j + 2];
        int r3 = g_bucket[s + j + 3];
        uint2 w0 = *reinterpret_cast<const uint2*>(g_xq + (size_t)r0 * DDIM + lane * 4);
        uint2 w1 = *reinterpret_cast<const uint2*>(g_xq + (size_t)r1 * DDIM + lane * 4);
        uint2 w2 = *reinterpret_cast<const uint2*>(g_xq + (size_t)r2 * DDIM + lane * 4);
        uint2 w3 = *reinterpret_cast<const uint2*>(g_xq + (size_t)r3 * DDIM + lane * 4);
        a0 += (int)(short)(w0.x) + (int)(short)(w1.x) + (int)(short)(w2.x) + (int)(short)(w3.x);
        a1 += ((int)w0.x >> 16) + ((int)w1.x >> 16) + ((int)w2.x >> 16) + ((int)w3.x >> 16);
        a2 += (int)(short)(w0.y) + (int)(short)(w1.y) + (int)(short)(w2.y) + (int)(short)(w3.y);
        a3 += ((int)w0.y >> 16) + ((int)w1.y >> 16) + ((int)w2.y >> 16) + ((int)w3.y >> 16);
    }
    for (; j < d; j++) {
        int r = g_bucket[s + j];
        uint2 w0 = *reinterpret_cast<const uint2*>(g_xq + (size_t)r * DDIM + lane * 4);
        a0 += (int)(short)(w0.x);
        a1 += ((int)w0.x >> 16);
        a2 += (int)(short)(w0.y);
        a3 += ((int)w0.y >> 16);
    }
    float rd = XQ_INV / fmaxf((float)d, 1.0f);
    float4 o = make_float4((float)a0 * rd, (float)a1 * rd,
                           (float)a2 * rd, (float)a3 * rd);
    *reinterpret_cast<float4*>(g_agg + (size_t)w * DDIM + lane * 4) = o;
    if (lane == 0) g_degi[w] = 0;      // restore zero-invariant for next call
}

// ---------------- fused GEMM + ReLU + LayerNorm (fp16 2-pass) ---------------
// CTA tile 64x128, 256 threads, 8 warps as 2(m) x 4(n); 2 CTAs/SM.
#define A_STRIDE_B 272          // 128 fp16 + 16B pad
#define B_STRIDE_B 528          // 256 fp16 + 16B pad
#define TILE_M    64
#define SM_BIAS   0
#define SM_GAMMA  512
#define SM_BETA   1024
#define SM_AH     1536
#define SM_AL     (SM_AH + TILE_M * A_STRIDE_B)     // 18944
#define SM_BF     (SM_AL + TILE_M * A_STRIDE_B)     // 36352
#define SM_TOTAL  (SM_BF + 128 * B_STRIDE_B)        // 103936 B  -> 2 CTAs/SM
#define SM_STAGE  SM_AH                              // 64*132*4 = 33792 B fits AH..AL

__device__ __forceinline__ uint32_t smem_u32(const void* p) {
    uint32_t a;
    asm("{ .reg .u64 t; cvta.to.shared.u64 t, %1; cvt.u32.u64 %0, t; }"
        : "=r"(a) : "l"(p));
    return a;
}
__device__ __forceinline__ void ldmx4(uint32_t* r, uint32_t addr) {
    asm volatile("ldmatrix.sync.aligned.m8n8.x4.shared.b16 {%0,%1,%2,%3}, [%4];"
                 : "=r"(r[0]), "=r"(r[1]), "=r"(r[2]), "=r"(r[3]) : "r"(addr));
}
__device__ __forceinline__ void mma_f16(float* c, const uint32_t* a, uint32_t b0, uint32_t b1) {
    asm volatile(
        "mma.sync.aligned.m16n8k16.row.col.f32.f16.f16.f32 "
        "{%0,%1,%2,%3}, {%4,%5,%6,%7}, {%8,%9}, {%0,%1,%2,%3};"
        : "+f"(c[0]), "+f"(c[1]), "+f"(c[2]), "+f"(c[3])
        : "r"(a[0]), "r"(a[1]), "r"(a[2]), "r"(a[3]), "r"(b0), "r"(b1));
}

__global__ __launch_bounds__(256, 2) void mma_gemm_kernel(
    const float* __restrict__ x,
    const float* __restrict__ gamma,
    const float* __restrict__ beta,
    float* __restrict__ out,
    int M)
{
    extern __shared__ char smem[];
    const uint32_t sb = smem_u32(smem);
    const int tid  = threadIdx.x;
    const int wid  = tid >> 5;
    const int lane = tid & 31;
    const int base_row = blockIdx.x * TILE_M;
    const int warp_m = wid & 1;      // 2 m-groups of 32 rows
    const int warp_n = wid >> 1;     // 4 n-groups of 32 cols

    if (tid < 32) {
        reinterpret_cast<float4*>(smem + SM_BIAS)[tid]  =
            reinterpret_cast<const float4*>(g_bc)[tid];
        reinterpret_cast<float4*>(smem + SM_GAMMA)[tid] =
            reinterpret_cast<const float4*>(gamma)[tid];
        reinterpret_cast<float4*>(smem + SM_BETA)[tid]  =
            reinterpret_cast<const float4*>(beta)[tid];
    }
    // B fp16 -> smem: 128 rows x 512B
    #pragma unroll
    for (int i = 0; i < 16; i++) {
        int idx = tid + i * 256;            // 0..4095 uint4
        int n = idx >> 5, q = idx & 31;
        *reinterpret_cast<uint4*>(smem + SM_BF + n * B_STRIDE_B + q * 16) =
            *reinterpret_cast<const uint4*>(g_Bf + n * 256 + q * 8);
    }

    // convert float4 -> fp16 hi/lo and store to A images
    auto cvt_store = [&](float4 v, int row, int kq) {
        __half h0 = __float2half_rn(v.x);
        __half h1 = __float2half_rn(v.y);
        __half h2 = __float2half_rn(v.z);
        __half h3 = __float2half_rn(v.w);
        __half l0 = __float2half_rn(v.x - __half2float(h0));
        __half l1 = __float2half_rn(v.y - __half2float(h1));
        __half l2 = __float2half_rn(v.z - __half2float(h2));
        __half l3 = __float2half_rn(v.w - __half2float(h3));
        uint2 hw, lw;
        hw.x = ((uint32_t)__half_as_ushort(h1) << 16) | __half_as_ushort(h0);
        hw.y = ((uint32_t)__half_as_ushort(h3) << 16) | __half_as_ushort(h2);
        lw.x = ((uint32_t)__half_as_ushort(l1) << 16) | __half_as_ushort(l0);
        lw.y = ((uint32_t)__half_as_ushort(l3) << 16) | __half_as_ushort(l2);
        uint32_t off = (uint32_t)row * A_STRIDE_B + (uint32_t)kq * 2;
        *reinterpret_cast<uint2*>(smem + SM_AH + off) = hw;
        *reinterpret_cast<uint2*>(smem + SM_AL + off) = lw;
    };

    // fill x half: 64 rows x 32 float4 = 2048 slots
    #pragma unroll
    for (int i = 0; i < 8; i++) {
        int idx = tid + i * 256;
        int row = idx >> 5;
        int kq  = (idx & 31) * 4;
        int grow = base_row + row;
        if (grow >= M) grow = M - 1;
        cvt_store(*reinterpret_cast<const float4*>(x + (size_t)grow * DDIM + kq), row, kq);
    }
    __syncthreads();

    // prefetch agg half into registers
    float4 pre[8];
    #pragma unroll
    for (int i = 0; i < 8; i++) {
        int idx = tid + i * 256;
        int row = idx >> 5;
        int kq  = (idx & 31) * 4;
        int grow = base_row + row;
        if (grow >= M) grow = M - 1;
        pre[i] = *reinterpret_cast<const float4*>(g_agg + (size_t)grow * DDIM + kq);
    }

    float acc[2][4][4];
    #pragma unroll
    for (int i = 0; i < 2; i++)
        #pragma unroll
        for (int j = 0; j < 4; j++)
            #pragma unroll
            for (int c = 0; c < 4; c++) acc[i][j][c] = 0.f;

    const int a_row_lo = (lane & 7) + ((lane >> 3) & 1) * 8;
    const int a_koff   = ((lane >> 4) & 1) * 8;
    const int b_nrow   = warp_n * 32 + (lane & 7) + ((lane >> 4) & 1) * 8;
    const int b_koff   = ((lane >> 3) & 1) * 8;

    auto compute_half = [&](int h) {
        #pragma unroll
        for (int kc = 0; kc < 8; kc++) {
            const int kA = kc * 16 + a_koff;
            const int kB = h * 128 + kc * 16 + b_koff;
            uint32_t ah[2][4], al[2][4];
            #pragma unroll
            for (int i = 0; i < 2; i++) {
                int row = warp_m * 32 + i * 16 + a_row_lo;
                uint32_t off = (uint32_t)row * A_STRIDE_B + (uint32_t)kA * 2;
                ldmx4(ah[i], sb + SM_AH + off);
                ldmx4(al[i], sb + SM_AL + off);
            }
            uint32_t bf[2][4];
            #pragma unroll
            for (int p = 0; p < 2; p++) {
                uint32_t off = (uint32_t)(b_nrow + p * 16) * B_STRIDE_B + (uint32_t)kB * 2;
                ldmx4(bf[p], sb + SM_BF + off);
            }
            #pragma unroll
            for (int i = 0; i < 2; i++)
                #pragma unroll
                for (int p = 0; p < 2; p++) {
                    mma_f16(acc[i][2 * p],     ah[i], bf[p][0], bf[p][1]);
                    mma_f16(acc[i][2 * p + 1], ah[i], bf[p][2], bf[p][3]);
                    mma_f16(acc[i][2 * p],     al[i], bf[p][0], bf[p][1]);
                    mma_f16(acc[i][2 * p + 1], al[i], bf[p][2], bf[p][3]);
                }
        }
    };

    compute_half(0);
    __syncthreads();            // all warps done reading x images

    // store prefetched agg half
    #pragma unroll
    for (int i = 0; i < 8; i++) {
        int idx = tid + i * 256;
        int row = idx >> 5;
        int kq  = (idx & 31) * 4;
        cvt_store(pre[i], row, kq);
    }
    __syncthreads();
    compute_half(1);
    __syncthreads();

    // stage accumulators [64][132] (reuses A region)
    float* stg = reinterpret_cast<float*>(smem + SM_STAGE);
    #pragma unroll
    for (int i = 0; i < 2; i++) {
        int row0 = warp_m * 32 + i * 16 + (lane >> 2);
        #pragma unroll
        for (int j = 0; j < 4; j++) {
            int col = warp_n * 32 + j * 8 + (lane & 3) * 2;
            *reinterpret_cast<float2*>(stg + row0 * 132 + col) =
                make_float2(acc[i][j][0], acc[i][j][1]);
            *reinterpret_cast<float2*>(stg + (row0 + 8) * 132 + col) =
                make_float2(acc[i][j][2], acc[i][j][3]);
        }
    }
    __syncthreads();

    // bias + ReLU + LN; warp wid -> rows wid*8..+7, lane owns 4 cols
    float4 b4 = *reinterpret_cast<const float4*>(smem + SM_BIAS  + lane * 16);
    float4 g4 = *reinterpret_cast<const float4*>(smem + SM_GAMMA + lane * 16);
    float4 t4 = *reinterpret_cast<const float4*>(smem + SM_BETA  + lane * 16);
    #pragma unroll
    for (int ii = 0; ii < 8; ii++) {
        int r = wid * 8 + ii;
        int grow = base_row + r;
        if (grow >= M) continue;
        float4 v = *reinterpret_cast<const float4*>(stg + r * 132 + lane * 4);
        v.x = fmaxf(v.x + b4.x, 0.f);
        v.y = fmaxf(v.y + b4.y, 0.f);
        v.z = fmaxf(v.z + b4.z, 0.f);
        v.w = fmaxf(v.w + b4.w, 0.f);
        float s  = v.x + v.y + v.z + v.w;
        float sq = v.x * v.x + v.y * v.y + v.z * v.z + v.w * v.w;
        #pragma unroll
        for (int o = 16; o > 0; o >>= 1) {
            s  += __shfl_xor_sync(0xFFFFFFFFu, s, o);
            sq += __shfl_xor_sync(0xFFFFFFFFu, sq, o);
        }
        float mean = s * (1.0f / DDIM);
        float var  = sq * (1.0f / DDIM) - mean * mean;
        float rstd = rsqrtf(var + 1e-5f);
        float4 o;
        o.x = (v.x - mean) * rstd * g4.x + t4.x;
        o.y = (v.y - mean) * rstd * g4.y + t4.y;
        o.z = (v.z - mean) * rstd * g4.z + t4.z;
        o.w = (v.w - mean) * rstd * g4.w + t4.w;
        *reinterpret_cast<float4*>(out + (size_t)grow * DDIM + lane * 4) = o;
    }
}

// ---------------------------------------------------------------------------
extern "C" void kernel_launch(void* const* d_in, const int* in_sizes, int n_in,
                              void* d_out, int out_size)
{
    const float* x     = (const float*)d_in[0];
    const int*   ei    = (const int*)d_in[1];
    const float* aggW  = (const float*)d_in[2];
    const float* aggb  = (const float*)d_in[3];
    const float* W     = (const float*)d_in[4];
    const float* b     = (const float*)d_in[5];
    const float* gamma = (const float*)d_in[6];
    const float* beta  = (const float*)d_in[7];
    float* out = (float*)d_out;

    const int E = in_sizes[1] / 2;
    const int M = in_sizes[0] / DDIM;

    cudaFuncSetAttribute(mma_gemm_kernel,
                         cudaFuncAttributeMaxDynamicSharedMemorySize, SM_TOTAL);

    const int* erow = ei;
    const int* ecol = ei + E;
    const int eb = (E + 255) / 256;
    const int nquad = (M * DDIM) / 8;
    const int pb = (nquad + 255) / 256;
    const int bb = (128 * 256 + 255) / 256;

    k1_kernel<<<eb + 64 + pb, 256>>>(ecol, E, eb, aggW, aggb, W, b, x, nquad);
    scan_kernel<<<1, 1024>>>(M);
    k2_kernel<<<eb + bb, 256>>>(erow, ecol, E, eb, W);
    gather_kernel<<<(M * 32 + 255) / 256, 256>>>(M);
    mma_gemm_kernel<<<(M + TILE_M - 1) / TILE_M, 256, SM_TOTAL>>>(x, gamma, beta, out, M);
}